// round 1
// baseline (speedup 1.0000x reference)
#include <cuda_runtime.h>
#include <math.h>

#define BB 2
#define XL 256
#define CL 767
#define YL 768
#define SS 1024
#define DD 1024
#define FFD 4096
#define NLAYER 6
#define NH 16
#define DH 64
#define CVOC 1025
#define EOS_ID 1024
#define BOS_ID 1025
#define MROWS (BB*SS)

// ---------------- scratch (static device globals; no allocs) ----------------
__device__ float g_h[BB*SS*DD];          // 8 MB  residual stream
__device__ float g_qkv[BB*SS*3*DD];      // 24 MB
__device__ float g_attn[BB*SS*DD];       // 8 MB  (also reused as gathered proj input)
__device__ float g_tmp[BB*SS*DD];        // 8 MB
__device__ float g_ff[BB*SS*FFD];        // 32 MB
__device__ float g_scores[(size_t)BB*NH*SS*SS];  // 128 MB
__device__ float g_logits[BB*YL*CVOC];   // ~6.3 MB
__device__ float g_nll[BB*YL];

// ---------------- helpers ----------------
__device__ __forceinline__ float blk_reduce_max(float v, float* red) {
    int t = threadIdx.x;
    red[t] = v; __syncthreads();
    for (int s = 128; s > 0; s >>= 1) {
        if (t < s) red[t] = fmaxf(red[t], red[t + s]);
        __syncthreads();
    }
    float r = red[0]; __syncthreads();
    return r;
}
__device__ __forceinline__ float blk_reduce_sum(float v, float* red) {
    int t = threadIdx.x;
    red[t] = v; __syncthreads();
    for (int s = 128; s > 0; s >>= 1) {
        if (t < s) red[t] += red[t + s];
        __syncthreads();
    }
    float r = red[0]; __syncthreads();
    return r;
}

// ---------------- embedding + sinusoidal PE ----------------
__global__ void embed_kernel(const int* __restrict__ tokens, const int* __restrict__ codes,
                             const float* __restrict__ tok_emb, const float* __restrict__ audio_emb) {
    int row = blockIdx.x;            // b*SS + s
    int b = row / SS, s = row % SS;
    const float* src; int pos;
    if (s < XL) {
        src = tok_emb + (size_t)tokens[b*XL + s] * DD;
        pos = s;
    } else {
        int sy = s - XL;
        int id = (sy == 0) ? BOS_ID : codes[b*CL + sy - 1];
        src = audio_emb + (size_t)id * DD;
        pos = sy;
    }
    float* dst = g_h + (size_t)row * DD;
    const float kinv = 9.210340371976184f / (float)DD;   // ln(10000)/D
    for (int d = threadIdx.x; d < DD; d += blockDim.x) {
        float freq = expf(-(float)(d & ~1) * kinv);
        float ang  = (float)pos * freq;
        float pe   = (d & 1) ? cosf(ang) : sinf(ang);
        dst[d] = src[d] + pe;
    }
}

// ---------------- generic 128x128x8 SGEMM: C = A@W (+bias) (+relu) ----------------
// A: [M,K] row-major, W: [K,N] row-major, C: [M,N] row-major
__global__ void gemm128(float* __restrict__ C, const float* __restrict__ A,
                        const float* __restrict__ W, const float* __restrict__ bias,
                        int M, int K, int N, int relu) {
    __shared__ float As[8][128];   // transposed: As[k][m]
    __shared__ float Bs[8][128];   // Bs[k][n]

    int tid = threadIdx.x;
    int tx = tid & 15, ty = tid >> 4;
    int m0 = blockIdx.y * 128;
    int n0 = blockIdx.x * 128;
    bool nvec = ((N & 3) == 0);

    float acc[8][8];
#pragma unroll
    for (int i = 0; i < 8; i++)
#pragma unroll
        for (int j = 0; j < 8; j++) acc[i][j] = 0.f;

    int ar = tid >> 1;            // 0..127
    int ac = (tid & 1) * 4;       // 0 or 4
    int br = tid >> 5;            // 0..7
    int bc = (tid & 31) * 4;      // 0..124

    for (int k0 = 0; k0 < K; k0 += 8) {
        // load A tile (guard M), store transposed
        float4 av = make_float4(0.f, 0.f, 0.f, 0.f);
        if (m0 + ar < M)
            av = *(const float4*)(A + (size_t)(m0 + ar) * K + k0 + ac);
        As[ac + 0][ar] = av.x; As[ac + 1][ar] = av.y;
        As[ac + 2][ar] = av.z; As[ac + 3][ar] = av.w;

        // load B tile (guard N; vector path only if N%4==0)
        if (nvec && (n0 + bc + 3 < N)) {
            *(float4*)&Bs[br][bc] = *(const float4*)(W + (size_t)(k0 + br) * N + n0 + bc);
        } else {
#pragma unroll
            for (int j = 0; j < 4; j++) {
                int col = n0 + bc + j;
                Bs[br][bc + j] = (col < N) ? W[(size_t)(k0 + br) * N + col] : 0.f;
            }
        }
        __syncthreads();

#pragma unroll
        for (int k = 0; k < 8; k++) {
            float a[8], bb[8];
            *(float4*)(a)     = *(float4*)&As[k][ty * 8];
            *(float4*)(a + 4) = *(float4*)&As[k][ty * 8 + 4];
            *(float4*)(bb)     = *(float4*)&Bs[k][tx * 8];
            *(float4*)(bb + 4) = *(float4*)&Bs[k][tx * 8 + 4];
#pragma unroll
            for (int i = 0; i < 8; i++)
#pragma unroll
                for (int j = 0; j < 8; j++) acc[i][j] = fmaf(a[i], bb[j], acc[i][j]);
        }
        __syncthreads();
    }

    int row0 = m0 + ty * 8, col0 = n0 + tx * 8;
#pragma unroll
    for (int i = 0; i < 8; i++) {
        if (row0 + i >= M) break;
#pragma unroll
        for (int j = 0; j < 8; j++) {
            int col = col0 + j;
            if (col < N) {
                float v = acc[i][j] + (bias ? bias[col] : 0.f);
                if (relu) v = fmaxf(v, 0.f);
                C[(size_t)(row0 + i) * N + col] = v;
            }
        }
    }
}

// ---------------- attention scores: S = scale * Q K^T, masked ----------------
// grid: (SS/64 j-tiles, SS/64 i-tiles, BB*NH)
__global__ void attn_scores(const float* __restrict__ qkv) {
    int bh = blockIdx.z;
    int b = bh / NH, h = bh % NH;
    int i0 = blockIdx.y * 64, j0 = blockIdx.x * 64;
    float* out = g_scores + (size_t)bh * SS * SS;

    int tid = threadIdx.x;
    int tx = tid & 15, ty = tid >> 4;

    // tiles never straddle XL (64-aligned): fully masked fast path
    bool full_mask = (i0 < XL) ? (j0 >= XL) : (j0 > i0);
    if (full_mask) {
#pragma unroll
        for (int i = 0; i < 4; i++)
#pragma unroll
            for (int j = 0; j < 4; j++)
                out[(size_t)(i0 + ty * 4 + i) * SS + j0 + tx * 4 + j] = -1e30f;
        return;
    }

    __shared__ float Qs[64][65];
    __shared__ float Ks[64][65];

    // load 64x64 Q and K tiles (dh=64 contiguous)
#pragma unroll
    for (int chunk = 0; chunk < 4; chunk++) {
        int idx = tid + chunk * 256;
        int r = idx >> 4;
        int c = (idx & 15) * 4;
        const float* qp = qkv + (size_t)(b * SS + i0 + r) * (3 * DD) + h * DH + c;
        const float* kp = qkv + (size_t)(b * SS + j0 + r) * (3 * DD) + DD + h * DH + c;
        float4 qv = *(const float4*)qp;
        float4 kv = *(const float4*)kp;
        Qs[r][c] = qv.x; Qs[r][c+1] = qv.y; Qs[r][c+2] = qv.z; Qs[r][c+3] = qv.w;
        Ks[r][c] = kv.x; Ks[r][c+1] = kv.y; Ks[r][c+2] = kv.z; Ks[r][c+3] = kv.w;
    }
    __syncthreads();

    float acc[4][4];
#pragma unroll
    for (int i = 0; i < 4; i++)
#pragma unroll
        for (int j = 0; j < 4; j++) acc[i][j] = 0.f;

#pragma unroll 8
    for (int k = 0; k < 64; k++) {
        float a[4], bb[4];
#pragma unroll
        for (int i = 0; i < 4; i++) a[i] = Qs[ty * 4 + i][k];
#pragma unroll
        for (int j = 0; j < 4; j++) bb[j] = Ks[tx * 4 + j][k];
#pragma unroll
        for (int i = 0; i < 4; i++)
#pragma unroll
            for (int j = 0; j < 4; j++) acc[i][j] = fmaf(a[i], bb[j], acc[i][j]);
    }

    const float scale = 0.125f;  // 1/sqrt(64)
#pragma unroll
    for (int i = 0; i < 4; i++) {
        int gi = i0 + ty * 4 + i;
#pragma unroll
        for (int j = 0; j < 4; j++) {
            int gj = j0 + tx * 4 + j;
            bool ok = (gi < XL) ? (gj < XL) : (gj <= gi);
            out[(size_t)gi * SS + gj] = ok ? acc[i][j] * scale : -1e30f;
        }
    }
}

// ---------------- softmax over allowed prefix [0, Li) ----------------
__global__ void softmax_rows() {
    __shared__ float red[256];
    int row = blockIdx.x;            // bh*SS + i
    int i = row % SS;
    int Li = (i < XL) ? XL : (i + 1);
    float* p = g_scores + (size_t)row * SS;
    int tid = threadIdx.x;

    float lmax = -1e30f;
    for (int j = tid; j < Li; j += 256) lmax = fmaxf(lmax, p[j]);
    lmax = blk_reduce_max(lmax, red);

    float lsum = 0.f;
    for (int j = tid; j < Li; j += 256) {
        float e = expf(p[j] - lmax);
        p[j] = e;
        lsum += e;
    }
    lsum = blk_reduce_sum(lsum, red);
    float inv = 1.f / lsum;
    for (int j = tid; j < Li; j += 256) p[j] *= inv;
    for (int j = Li + tid; j < SS; j += 256) p[j] = 0.f;
}

// ---------------- attn output: O = P V (prefix-truncated K loop) ----------------
// grid: (SS/64 i-tiles, BB*NH)
__global__ void attn_pv(const float* __restrict__ qkv) {
    int bh = blockIdx.y;
    int b = bh / NH, h = bh % NH;
    int i0 = blockIdx.x * 64;
    int Jmax = (i0 + 63 < XL) ? XL : (i0 + 64);

    __shared__ float Ps[16][65];   // transposed: Ps[j][i]
    __shared__ float Vs[16][64];   // Vs[j][d]

    int tid = threadIdx.x;
    int tx = tid & 15, ty = tid >> 4;

    float acc[4][4];
#pragma unroll
    for (int i = 0; i < 4; i++)
#pragma unroll
        for (int j = 0; j < 4; j++) acc[i][j] = 0.f;

    int pr = tid >> 2;         // 0..63 (i)
    int pc = (tid & 3) * 4;    // 0..12 (j)
    int vr = tid >> 4;         // 0..15 (j)
    int vc = (tid & 15) * 4;   // 0..60 (d)

    for (int j0 = 0; j0 < Jmax; j0 += 16) {
        float4 pv = *(const float4*)(g_scores + ((size_t)bh * SS + i0 + pr) * SS + j0 + pc);
        Ps[pc + 0][pr] = pv.x; Ps[pc + 1][pr] = pv.y;
        Ps[pc + 2][pr] = pv.z; Ps[pc + 3][pr] = pv.w;
        *(float4*)&Vs[vr][vc] =
            *(const float4*)(qkv + (size_t)(b * SS + j0 + vr) * (3 * DD) + 2 * DD + h * DH + vc);
        __syncthreads();

#pragma unroll
        for (int k = 0; k < 16; k++) {
            float a[4], bb[4];
#pragma unroll
            for (int i = 0; i < 4; i++) a[i] = Ps[k][ty * 4 + i];
#pragma unroll
            for (int j = 0; j < 4; j++) bb[j] = Vs[k][tx * 4 + j];
#pragma unroll
            for (int i = 0; i < 4; i++)
#pragma unroll
                for (int j = 0; j < 4; j++) acc[i][j] = fmaf(a[i], bb[j], acc[i][j]);
        }
        __syncthreads();
    }

#pragma unroll
    for (int i = 0; i < 4; i++)
#pragma unroll
        for (int j = 0; j < 4; j++)
            g_attn[(size_t)(b * SS + i0 + ty * 4 + i) * DD + h * DH + tx * 4 + j] = acc[i][j];
}

// ---------------- dst = LayerNorm(x + add) ----------------
__global__ void add_ln(float* __restrict__ dst, const float* __restrict__ x,
                       const float* __restrict__ addv, const float* __restrict__ w,
                       const float* __restrict__ bvec) {
    __shared__ float buf[DD];
    __shared__ float red[256];
    int row = blockIdx.x;
    int tid = threadIdx.x;
    const float* xr = x + (size_t)row * DD;
    const float* ar = addv ? (addv + (size_t)row * DD) : nullptr;

    float lsum = 0.f;
    for (int d = tid; d < DD; d += 256) {
        float v = xr[d] + (ar ? ar[d] : 0.f);
        buf[d] = v;
        lsum += v;
    }
    float mu = blk_reduce_sum(lsum, red) * (1.f / DD);

    float lsq = 0.f;
    for (int d = tid; d < DD; d += 256) {
        float t = buf[d] - mu;
        lsq += t * t;
    }
    float var = blk_reduce_sum(lsq, red) * (1.f / DD);
    float rstd = rsqrtf(var + 1e-5f);

    float* dr = dst + (size_t)row * DD;
    for (int d = tid; d < DD; d += 256)
        dr[d] = (buf[d] - mu) * rstd * w[d] + bvec[d];
}

// ---------------- gather audio rows for projection ----------------
__global__ void gather_rows() {
    int m = blockIdx.x;
    int b = m / YL, t = m % YL;
    const float* src = g_h + (size_t)(b * SS + XL + t) * DD;
    float* dst = g_attn + (size_t)m * DD;
    for (int d = threadIdx.x; d < DD; d += blockDim.x) dst[d] = src[d];
}

// ---------------- per-row NLL ----------------
__global__ void nll_kernel(const int* __restrict__ codes) {
    __shared__ float red[256];
    int m = blockIdx.x;
    int b = m / YL, t = m % YL;
    const float* row = g_logits + (size_t)m * CVOC;
    int tid = threadIdx.x;

    float lmax = -1e30f;
    for (int j = tid; j < CVOC; j += 256) lmax = fmaxf(lmax, row[j]);
    lmax = blk_reduce_max(lmax, red);

    float lsum = 0.f;
    for (int j = tid; j < CVOC; j += 256) lsum += expf(row[j] - lmax);
    lsum = blk_reduce_sum(lsum, red);

    if (tid == 0) {
        int tgt = (t < CL) ? codes[b * CL + t] : EOS_ID;
        g_nll[m] = lmax + logf(lsum) - row[tgt];
    }
}

__global__ void mean_kernel(float* __restrict__ out) {
    __shared__ float red[256];
    int tid = threadIdx.x;
    float s = 0.f;
    for (int i = tid; i < BB * YL; i += 256) s += g_nll[i];
    s = blk_reduce_sum(s, red);
    if (tid == 0) out[0] = s / (float)(BB * YL);
}

// ---------------- launch ----------------
extern "C" void kernel_launch(void* const* d_in, const int* in_sizes, int n_in,
                              void* d_out, int out_size) {
    const int*   tokens    = (const int*)d_in[0];
    const int*   codes     = (const int*)d_in[1];
    const float* tok_emb   = (const float*)d_in[2];
    const float* audio_emb = (const float*)d_in[3];
    const float* Wqkv      = (const float*)d_in[4];
    const float* b_qkv     = (const float*)d_in[5];
    const float* Wo        = (const float*)d_in[6];
    const float* b_o       = (const float*)d_in[7];
    const float* W1        = (const float*)d_in[8];
    const float* b1        = (const float*)d_in[9];
    const float* W2        = (const float*)d_in[10];
    const float* b2        = (const float*)d_in[11];
    const float* ln1_w     = (const float*)d_in[12];
    const float* ln1_b     = (const float*)d_in[13];
    const float* ln2_w     = (const float*)d_in[14];
    const float* ln2_b     = (const float*)d_in[15];
    const float* lnf_w     = (const float*)d_in[16];
    const float* lnf_b     = (const float*)d_in[17];
    const float* proj_w    = (const float*)d_in[18];

    float *hP, *qkvP, *attnP, *tmpP, *ffP, *logitsP;
    cudaGetSymbolAddress((void**)&hP, g_h);
    cudaGetSymbolAddress((void**)&qkvP, g_qkv);
    cudaGetSymbolAddress((void**)&attnP, g_attn);
    cudaGetSymbolAddress((void**)&tmpP, g_tmp);
    cudaGetSymbolAddress((void**)&ffP, g_ff);
    cudaGetSymbolAddress((void**)&logitsP, g_logits);

    embed_kernel<<<BB * SS, 256>>>(tokens, codes, tok_emb, audio_emb);

    for (int l = 0; l < NLAYER; l++) {
        const float* Wqkv_l = Wqkv + (size_t)l * DD * 3 * DD;
        const float* bq_l   = b_qkv + (size_t)l * 3 * DD;
        const float* Wo_l   = Wo + (size_t)l * DD * DD;
        const float* bo_l   = b_o + (size_t)l * DD;
        const float* W1_l   = W1 + (size_t)l * DD * FFD;
        const float* b1_l   = b1 + (size_t)l * FFD;
        const float* W2_l   = W2 + (size_t)l * FFD * DD;
        const float* b2_l   = b2 + (size_t)l * DD;

        gemm128<<<dim3(3 * DD / 128, MROWS / 128), 256>>>(qkvP, hP, Wqkv_l, bq_l, MROWS, DD, 3 * DD, 0);
        attn_scores<<<dim3(SS / 64, SS / 64, BB * NH), 256>>>(qkvP);
        softmax_rows<<<BB * NH * SS, 256>>>();
        attn_pv<<<dim3(SS / 64, BB * NH), 256>>>(qkvP);
        gemm128<<<dim3(DD / 128, MROWS / 128), 256>>>(tmpP, attnP, Wo_l, bo_l, MROWS, DD, DD, 0);
        add_ln<<<MROWS, 256>>>(hP, hP, tmpP, ln1_w + l * DD, ln1_b + l * DD);
        gemm128<<<dim3(FFD / 128, MROWS / 128), 256>>>(ffP, hP, W1_l, b1_l, MROWS, DD, FFD, 1);
        gemm128<<<dim3(DD / 128, MROWS / 128), 256>>>(tmpP, ffP, W2_l, b2_l, MROWS, FFD, DD, 0);
        add_ln<<<MROWS, 256>>>(hP, hP, tmpP, ln2_w + l * DD, ln2_b + l * DD);
    }

    add_ln<<<MROWS, 256>>>(hP, hP, nullptr, lnf_w, lnf_b);
    gather_rows<<<BB * YL, 256>>>();
    gemm128<<<dim3((CVOC + 127) / 128, (BB * YL) / 128), 256>>>(logitsP, attnP, proj_w, nullptr,
                                                                 BB * YL, DD, CVOC, 0);
    nll_kernel<<<BB * YL, 256>>>(codes);
    mean_kernel<<<1, 256>>>((float*)d_out);
}

// round 3
// speedup vs baseline: 3.9577x; 3.9577x over previous
#include <cuda_runtime.h>
#include <cuda_bf16.h>
#include <math.h>
#include <stdint.h>

#define BB 2
#define XL 256
#define CL 767
#define YL 768
#define SS 1024
#define DD 1024
#define FFD 4096
#define NLAYER 6
#define NH 16
#define DH 64
#define CVOC 1025
#define NPAD 1152
#define EOS_ID 1024
#define BOS_ID 1025
#define MROWS (BB*SS)
#define PROWS (BB*YL)

// ---------------- scratch (static device globals; no allocs) ----------------
__device__ float g_h[MROWS*DD];
__device__ __nv_bfloat16 g_hb[MROWS*DD];
__device__ float g_qkv[MROWS*3*DD];
__device__ __nv_bfloat16 g_attnb[MROWS*DD];
__device__ float g_tmp[MROWS*DD];
__device__ __nv_bfloat16 g_ffb[MROWS*FFD];
__device__ __nv_bfloat16 g_xb[PROWS*DD];
__device__ float g_scores[(size_t)BB*NH*SS*SS];
__device__ float g_logits[PROWS*NPAD];
__device__ float g_nll[PROWS];
__device__ __nv_bfloat16 g_WqkvT[NLAYER*3*DD*DD];
__device__ __nv_bfloat16 g_WoT[NLAYER*DD*DD];
__device__ __nv_bfloat16 g_W1T[NLAYER*FFD*DD];
__device__ __nv_bfloat16 g_W2T[NLAYER*DD*FFD];
__device__ __nv_bfloat16 g_projT[NPAD*DD];

// ---------------- helpers ----------------
__device__ __forceinline__ uint32_t smem_u32(const void* p) {
    uint32_t a;
    asm("{ .reg .u64 t; cvta.to.shared.u64 t, %1; cvt.u32.u64 %0, t; }" : "=r"(a) : "l"(p));
    return a;
}
__device__ __forceinline__ void cp16(void* smem_dst, const void* gsrc) {
    uint32_t s = smem_u32(smem_dst);
    asm volatile("cp.async.cg.shared.global [%0], [%1], 16;" :: "r"(s), "l"(gsrc));
}
__device__ __forceinline__ void cp_commit() { asm volatile("cp.async.commit_group;" ::: "memory"); }
__device__ __forceinline__ void cp_wait0()  { asm volatile("cp.async.wait_group 0;" ::: "memory"); }

__device__ __forceinline__ void ldm_x4(uint32_t* r, uint32_t addr) {
    asm volatile("ldmatrix.sync.aligned.m8n8.x4.shared.b16 {%0,%1,%2,%3}, [%4];"
        : "=r"(r[0]), "=r"(r[1]), "=r"(r[2]), "=r"(r[3]) : "r"(addr));
}
__device__ __forceinline__ void mma16816(float* c, const uint32_t* a, const uint32_t* b) {
    asm volatile("mma.sync.aligned.m16n8k16.row.col.f32.bf16.bf16.f32 "
        "{%0,%1,%2,%3}, {%4,%5,%6,%7}, {%8,%9}, {%0,%1,%2,%3};"
        : "+f"(c[0]), "+f"(c[1]), "+f"(c[2]), "+f"(c[3])
        : "r"(a[0]), "r"(a[1]), "r"(a[2]), "r"(a[3]), "r"(b[0]), "r"(b[1]));
}

#define KCH 64
#define PADW 72                       // padded row width in bf16 elems (144 B)
#define TILE_E (128*PADW)             // elems per tile buffer
#define GEMM_SMEM (4*TILE_E*2 + 512)  // A0,A1,B0,B1 + bias

// ---------------- HMMA bf16 GEMM: C[M,N] = A[M,K] @ Wt[N,K]^T (+bias)(+relu) ----------------
// grid (N/128, M/128), block 256 (8 warps: 2 M x 4 N; warp tile 64x32)
template<int OUT_BF16, int RELU, int HAS_BIAS>
__global__ void __launch_bounds__(256) gemm_mma(void* __restrict__ Cv,
        const __nv_bfloat16* __restrict__ A, const __nv_bfloat16* __restrict__ Wt,
        const float* __restrict__ bias, int M, int K, int N) {
    extern __shared__ __nv_bfloat16 sm[];
    __nv_bfloat16* As = sm;                 // [2][TILE_E]
    __nv_bfloat16* Bs = sm + 2 * TILE_E;    // [2][TILE_E]
    float* biasSm = (float*)(sm + 4 * TILE_E);

    int tid = threadIdx.x;
    int wid = tid >> 5, lane = tid & 31;
    int wm = wid >> 2, wn = wid & 3;        // warp coords: 2 x 4
    int m0 = blockIdx.y * 128, n0 = blockIdx.x * 128;

    if (HAS_BIAS && tid < 128) biasSm[tid] = bias[n0 + tid];

    const size_t rsA = (size_t)K;           // row stride elems
    const __nv_bfloat16* gA = A + (size_t)m0 * K;
    const __nv_bfloat16* gB = Wt + (size_t)n0 * K;

    float acc[4][4][4];
#pragma unroll
    for (int i = 0; i < 4; i++)
#pragma unroll
        for (int j = 0; j < 4; j++)
#pragma unroll
            for (int q = 0; q < 4; q++) acc[i][j][q] = 0.f;

    const int nch = K / KCH;

    // chunk load helper indices: c = tid + 256*i -> row=c>>3, 16B piece (c&7)
    // prologue: chunk 0 into buf 0
#pragma unroll
    for (int i = 0; i < 4; i++) {
        int c = tid + 256 * i;
        int row = c >> 3, cc = c & 7;
        cp16(As + row * PADW + cc * 8, gA + (size_t)row * rsA + cc * 8);
        cp16(Bs + row * PADW + cc * 8, gB + (size_t)row * rsA + cc * 8);
    }
    cp_commit();

    // ldmatrix lane addressing (within-tile offsets)
    int a_r = (lane & 7) + ((lane >> 3) & 1) * 8;   // row within m16 tile
    int a_ch = (lane >> 4) * 8;                      // k half
    int b_r = (lane & 7) + (lane >> 4) * 8;          // n row within 16
    int b_ch = ((lane >> 3) & 1) * 8;                // k half

    for (int ic = 0; ic < nch; ic++) {
        int buf = ic & 1;
        cp_wait0();
        __syncthreads();
        if (ic + 1 < nch) {
            const __nv_bfloat16* gA1 = gA + (size_t)(ic + 1) * KCH;
            const __nv_bfloat16* gB1 = gB + (size_t)(ic + 1) * KCH;
            __nv_bfloat16* dA = As + (buf ^ 1) * TILE_E;
            __nv_bfloat16* dB = Bs + (buf ^ 1) * TILE_E;
#pragma unroll
            for (int i = 0; i < 4; i++) {
                int c = tid + 256 * i;
                int row = c >> 3, cc = c & 7;
                cp16(dA + row * PADW + cc * 8, gA1 + (size_t)row * rsA + cc * 8);
                cp16(dB + row * PADW + cc * 8, gB1 + (size_t)row * rsA + cc * 8);
            }
            cp_commit();
        }

        const __nv_bfloat16* As_ = As + buf * TILE_E;
        const __nv_bfloat16* Bs_ = Bs + buf * TILE_E;
#pragma unroll
        for (int ks = 0; ks < 4; ks++) {
            int koff = ks * 16;
            uint32_t a[4][4], b[2][4];
#pragma unroll
            for (int mi = 0; mi < 4; mi++) {
                uint32_t addr = smem_u32(As_ + (size_t)(wm * 64 + mi * 16 + a_r) * PADW + koff + a_ch);
                ldm_x4(a[mi], addr);
            }
#pragma unroll
            for (int ni2 = 0; ni2 < 2; ni2++) {
                uint32_t addr = smem_u32(Bs_ + (size_t)(wn * 32 + ni2 * 16 + b_r) * PADW + koff + b_ch);
                ldm_x4(b[ni2], addr);
            }
#pragma unroll
            for (int mi = 0; mi < 4; mi++)
#pragma unroll
                for (int ni = 0; ni < 4; ni++)
                    mma16816(acc[mi][ni], a[mi], b[ni >> 1] + (ni & 1) * 2);
        }
        __syncthreads();
    }

    // epilogue
    int rg = lane >> 2, cg = (lane & 3) * 2;
#pragma unroll
    for (int mi = 0; mi < 4; mi++) {
#pragma unroll
        for (int ni = 0; ni < 4; ni++) {
            int colL = wn * 32 + ni * 8 + cg;        // col within block
            int col = n0 + colL;
            float b0 = HAS_BIAS ? biasSm[colL] : 0.f;
            float b1 = HAS_BIAS ? biasSm[colL + 1] : 0.f;
#pragma unroll
            for (int rh = 0; rh < 2; rh++) {
                int row = m0 + wm * 64 + mi * 16 + rg + rh * 8;
                float v0 = acc[mi][ni][rh * 2 + 0] + b0;
                float v1 = acc[mi][ni][rh * 2 + 1] + b1;
                if (RELU) { v0 = fmaxf(v0, 0.f); v1 = fmaxf(v1, 0.f); }
                if (OUT_BF16) {
                    __nv_bfloat162 p = __floats2bfloat162_rn(v0, v1);
                    *(__nv_bfloat162*)((__nv_bfloat16*)Cv + (size_t)row * N + col) = p;
                } else {
                    *(float2*)((float*)Cv + (size_t)row * N + col) = make_float2(v0, v1);
                }
            }
        }
    }
}

// ---------------- weight fp32[K,N] -> bf16 transposed [Nt,K] ----------------
__global__ void wconv(const float* __restrict__ W, __nv_bfloat16* __restrict__ Wt,
                      int K, int N, int Nt) {
    __shared__ float t[32][33];
    int n0 = blockIdx.x * 32, k0 = blockIdx.y * 32;
    int tx = threadIdx.x, ty = threadIdx.y;
#pragma unroll
    for (int j = 0; j < 32; j += 8) {
        int n = n0 + tx, k = k0 + ty + j;
        t[ty + j][tx] = (n < N) ? W[(size_t)k * N + n] : 0.f;
    }
    __syncthreads();
#pragma unroll
    for (int j = 0; j < 32; j += 8) {
        int n = n0 + ty + j, k = k0 + tx;
        if (n < Nt) Wt[(size_t)n * K + k] = __float2bfloat16(t[tx][ty + j]);
    }
}

// ---------------- block reductions ----------------
__device__ __forceinline__ float blk_reduce_max(float v, float* red) {
    int t = threadIdx.x;
    red[t] = v; __syncthreads();
    for (int s = 128; s > 0; s >>= 1) { if (t < s) red[t] = fmaxf(red[t], red[t + s]); __syncthreads(); }
    float r = red[0]; __syncthreads();
    return r;
}
__device__ __forceinline__ float blk_reduce_sum(float v, float* red) {
    int t = threadIdx.x;
    red[t] = v; __syncthreads();
    for (int s = 128; s > 0; s >>= 1) { if (t < s) red[t] += red[t + s]; __syncthreads(); }
    float r = red[0]; __syncthreads();
    return r;
}

// ---------------- embedding + sinusoidal PE ----------------
__global__ void embed_kernel(const int* __restrict__ tokens, const int* __restrict__ codes,
                             const float* __restrict__ tok_emb, const float* __restrict__ audio_emb) {
    int row = blockIdx.x;
    int b = row / SS, s = row % SS;
    const float* src; int pos;
    if (s < XL) { src = tok_emb + (size_t)tokens[b*XL + s] * DD; pos = s; }
    else {
        int sy = s - XL;
        int id = (sy == 0) ? BOS_ID : codes[b*CL + sy - 1];
        src = audio_emb + (size_t)id * DD; pos = sy;
    }
    float* dst = g_h + (size_t)row * DD;
    __nv_bfloat16* dstb = g_hb + (size_t)row * DD;
    const float kinv = 9.210340371976184f / (float)DD;
    for (int d = threadIdx.x; d < DD; d += blockDim.x) {
        float freq = expf(-(float)(d & ~1) * kinv);
        float ang = (float)pos * freq;
        float pe = (d & 1) ? cosf(ang) : sinf(ang);
        float v = src[d] + pe;
        dst[d] = v;
        dstb[d] = __float2bfloat16(v);
    }
}

// ---------------- attention scores ----------------
__global__ void attn_scores(const float* __restrict__ qkv) {
    int bh = blockIdx.z;
    int b = bh / NH, h = bh % NH;
    int i0 = blockIdx.y * 64, j0 = blockIdx.x * 64;
    bool full_mask = (i0 < XL) ? (j0 >= XL) : (j0 > i0);
    if (full_mask) return;

    float* out = g_scores + (size_t)bh * SS * SS;
    int tid = threadIdx.x;
    int tx = tid & 15, ty = tid >> 4;

    __shared__ float Qs[64][65];
    __shared__ float Ks[64][65];
#pragma unroll
    for (int chunk = 0; chunk < 4; chunk++) {
        int idx = tid + chunk * 256;
        int r = idx >> 4;
        int c = (idx & 15) * 4;
        float4 qv = *(const float4*)(qkv + (size_t)(b*SS + i0 + r) * (3*DD) + h*DH + c);
        float4 kv = *(const float4*)(qkv + (size_t)(b*SS + j0 + r) * (3*DD) + DD + h*DH + c);
        Qs[r][c] = qv.x; Qs[r][c+1] = qv.y; Qs[r][c+2] = qv.z; Qs[r][c+3] = qv.w;
        Ks[r][c] = kv.x; Ks[r][c+1] = kv.y; Ks[r][c+2] = kv.z; Ks[r][c+3] = kv.w;
    }
    __syncthreads();

    float acc[4][4];
#pragma unroll
    for (int i = 0; i < 4; i++)
#pragma unroll
        for (int j = 0; j < 4; j++) acc[i][j] = 0.f;
#pragma unroll 8
    for (int k = 0; k < 64; k++) {
        float a[4], bb[4];
#pragma unroll
        for (int i = 0; i < 4; i++) a[i] = Qs[ty*4+i][k];
#pragma unroll
        for (int j = 0; j < 4; j++) bb[j] = Ks[tx*4+j][k];
#pragma unroll
        for (int i = 0; i < 4; i++)
#pragma unroll
            for (int j = 0; j < 4; j++) acc[i][j] = fmaf(a[i], bb[j], acc[i][j]);
    }
    const float scale = 0.125f;
#pragma unroll
    for (int i = 0; i < 4; i++) {
        int gi = i0 + ty*4 + i;
#pragma unroll
        for (int j = 0; j < 4; j++) {
            int gj = j0 + tx*4 + j;
            bool ok = (gi < XL) ? (gj < XL) : (gj <= gi);
            out[(size_t)gi * SS + gj] = ok ? acc[i][j] * scale : -1e30f;
        }
    }
}

// ---------------- softmax over allowed prefix ----------------
__global__ void softmax_rows() {
    __shared__ float red[256];
    int row = blockIdx.x;
    int i = row % SS;
    int Li = (i < XL) ? XL : (i + 1);
    int zend = (i < XL) ? XL : (((i >> 6) + 1) << 6);
    float* p = g_scores + (size_t)row * SS;
    int tid = threadIdx.x;

    float lmax = -1e30f;
    for (int j = tid; j < Li; j += 256) lmax = fmaxf(lmax, p[j]);
    lmax = blk_reduce_max(lmax, red);
    float lsum = 0.f;
    for (int j = tid; j < Li; j += 256) { float e = expf(p[j] - lmax); p[j] = e; lsum += e; }
    lsum = blk_reduce_sum(lsum, red);
    float inv = 1.f / lsum;
    for (int j = tid; j < Li; j += 256) p[j] *= inv;
    for (int j = Li + tid; j < zend; j += 256) p[j] = 0.f;
}

// ---------------- O = P V (bf16 out) ----------------
__global__ void attn_pv(const float* __restrict__ qkv) {
    int bh = blockIdx.y;
    int b = bh / NH, h = bh % NH;
    int i0 = blockIdx.x * 64;
    int Jmax = (i0 + 63 < XL) ? XL : (i0 + 64);

    __shared__ float Ps[16][65];
    __shared__ float Vs[16][64];
    int tid = threadIdx.x;
    int tx = tid & 15, ty = tid >> 4;

    float acc[4][4];
#pragma unroll
    for (int i = 0; i < 4; i++)
#pragma unroll
        for (int j = 0; j < 4; j++) acc[i][j] = 0.f;

    int pr = tid >> 2, pc = (tid & 3) * 4;
    int vr = tid >> 4, vc = (tid & 15) * 4;

    for (int j0 = 0; j0 < Jmax; j0 += 16) {
        float4 pv = *(const float4*)(g_scores + ((size_t)bh*SS + i0 + pr) * SS + j0 + pc);
        Ps[pc+0][pr] = pv.x; Ps[pc+1][pr] = pv.y; Ps[pc+2][pr] = pv.z; Ps[pc+3][pr] = pv.w;
        *(float4*)&Vs[vr][vc] = *(const float4*)(qkv + (size_t)(b*SS + j0 + vr) * (3*DD) + 2*DD + h*DH + vc);
        __syncthreads();
#pragma unroll
        for (int k = 0; k < 16; k++) {
            float a[4], bb[4];
#pragma unroll
            for (int i = 0; i < 4; i++) a[i] = Ps[k][ty*4+i];
#pragma unroll
            for (int j = 0; j < 4; j++) bb[j] = Vs[k][tx*4+j];
#pragma unroll
            for (int i = 0; i < 4; i++)
#pragma unroll
                for (int j = 0; j < 4; j++) acc[i][j] = fmaf(a[i], bb[j], acc[i][j]);
        }
        __syncthreads();
    }
#pragma unroll
    for (int i = 0; i < 4; i++)
#pragma unroll
        for (int j = 0; j < 4; j++)
            g_attnb[(size_t)(b*SS + i0 + ty*4 + i) * DD + h*DH + tx*4 + j] = __float2bfloat16(acc[i][j]);
}

// ---------------- dst = LayerNorm(x + add), also bf16 copy ----------------
__global__ void add_ln(float* __restrict__ dst, __nv_bfloat16* __restrict__ dstb,
                       const float* __restrict__ x, const float* __restrict__ addv,
                       const float* __restrict__ w, const float* __restrict__ bvec) {
    __shared__ float buf[DD];
    __shared__ float red[256];
    int row = blockIdx.x;
    int tid = threadIdx.x;
    const float* xr = x + (size_t)row * DD;
    const float* ar = addv ? (addv + (size_t)row * DD) : nullptr;

    float lsum = 0.f;
    for (int d = tid; d < DD; d += 256) {
        float v = xr[d] + (ar ? ar[d] : 0.f);
        buf[d] = v; lsum += v;
    }
    float mu = blk_reduce_sum(lsum, red) * (1.f / DD);
    float lsq = 0.f;
    for (int d = tid; d < DD; d += 256) { float t = buf[d] - mu; lsq += t * t; }
    float var = blk_reduce_sum(lsq, red) * (1.f / DD);
    float rstd = rsqrtf(var + 1e-5f);

    float* dr = dst + (size_t)row * DD;
    __nv_bfloat16* db = dstb ? (dstb + (size_t)row * DD) : nullptr;
    for (int d = tid; d < DD; d += 256) {
        float v = (buf[d] - mu) * rstd * w[d] + bvec[d];
        dr[d] = v;
        if (db) db[d] = __float2bfloat16(v);
    }
}

// ---------------- gather audio rows (bf16) ----------------
__global__ void gather_rows() {
    int m = blockIdx.x;
    int b = m / YL, t = m % YL;
    const float* src = g_h + (size_t)(b*SS + XL + t) * DD;
    __nv_bfloat16* dst = g_xb + (size_t)m * DD;
    for (int d = threadIdx.x; d < DD; d += blockDim.x) dst[d] = __float2bfloat16(src[d]);
}

// ---------------- per-row NLL ----------------
__global__ void nll_kernel(const int* __restrict__ codes) {
    __shared__ float red[256];
    int m = blockIdx.x;
    int b = m / YL, t = m % YL;
    const float* row = g_logits + (size_t)m * NPAD;
    int tid = threadIdx.x;

    float lmax = -1e30f;
    for (int j = tid; j < CVOC; j += 256) lmax = fmaxf(lmax, row[j]);
    lmax = blk_reduce_max(lmax, red);
    float lsum = 0.f;
    for (int j = tid; j < CVOC; j += 256) lsum += expf(row[j] - lmax);
    lsum = blk_reduce_sum(lsum, red);
    if (tid == 0) {
        int tgt = (t < CL) ? codes[b*CL + t] : EOS_ID;
        g_nll[m] = lmax + logf(lsum) - row[tgt];
    }
}

__global__ void mean_kernel(float* __restrict__ out) {
    __shared__ float red[256];
    int tid = threadIdx.x;
    float s = 0.f;
    for (int i = tid; i < PROWS; i += 256) s += g_nll[i];
    s = blk_reduce_sum(s, red);
    if (tid == 0) out[0] = s / (float)PROWS;
}

// ---------------- launch ----------------
extern "C" void kernel_launch(void* const* d_in, const int* in_sizes, int n_in,
                              void* d_out, int out_size) {
    const int*   tokens    = (const int*)d_in[0];
    const int*   codes     = (const int*)d_in[1];
    const float* tok_emb   = (const float*)d_in[2];
    const float* audio_emb = (const float*)d_in[3];
    const float* Wqkv      = (const float*)d_in[4];
    const float* b_qkv     = (const float*)d_in[5];
    const float* Wo        = (const float*)d_in[6];
    const float* b_o       = (const float*)d_in[7];
    const float* W1        = (const float*)d_in[8];
    const float* b1        = (const float*)d_in[9];
    const float* W2        = (const float*)d_in[10];
    const float* b2        = (const float*)d_in[11];
    const float* ln1_w     = (const float*)d_in[12];
    const float* ln1_b     = (const float*)d_in[13];
    const float* ln2_w     = (const float*)d_in[14];
    const float* ln2_b     = (const float*)d_in[15];
    const float* lnf_w     = (const float*)d_in[16];
    const float* lnf_b     = (const float*)d_in[17];
    const float* proj_w    = (const float*)d_in[18];

    float *hP, *qkvP, *tmpP, *logitsP;
    __nv_bfloat16 *hbP, *attnbP, *ffbP, *xbP, *WqkvTP, *WoTP, *W1TP, *W2TP, *projTP;
    cudaGetSymbolAddress((void**)&hP, g_h);
    cudaGetSymbolAddress((void**)&hbP, g_hb);
    cudaGetSymbolAddress((void**)&qkvP, g_qkv);
    cudaGetSymbolAddress((void**)&attnbP, g_attnb);
    cudaGetSymbolAddress((void**)&tmpP, g_tmp);
    cudaGetSymbolAddress((void**)&ffbP, g_ffb);
    cudaGetSymbolAddress((void**)&xbP, g_xb);
    cudaGetSymbolAddress((void**)&logitsP, g_logits);
    cudaGetSymbolAddress((void**)&WqkvTP, g_WqkvT);
    cudaGetSymbolAddress((void**)&WoTP, g_WoT);
    cudaGetSymbolAddress((void**)&W1TP, g_W1T);
    cudaGetSymbolAddress((void**)&W2TP, g_W2T);
    cudaGetSymbolAddress((void**)&projTP, g_projT);

    cudaFuncSetAttribute(gemm_mma<0,0,1>, cudaFuncAttributeMaxDynamicSharedMemorySize, GEMM_SMEM);
    cudaFuncSetAttribute(gemm_mma<1,1,1>, cudaFuncAttributeMaxDynamicSharedMemorySize, GEMM_SMEM);
    cudaFuncSetAttribute(gemm_mma<0,0,0>, cudaFuncAttributeMaxDynamicSharedMemorySize, GEMM_SMEM);

    dim3 wb(32, 8);
    for (int l = 0; l < NLAYER; l++) {
        wconv<<<dim3(3*DD/32, DD/32), wb>>>(Wqkv + (size_t)l*DD*3*DD, WqkvTP + (size_t)l*3*DD*DD, DD, 3*DD, 3*DD);
        wconv<<<dim3(DD/32, DD/32), wb>>>(Wo + (size_t)l*DD*DD, WoTP + (size_t)l*DD*DD, DD, DD, DD);
        wconv<<<dim3(FFD/32, DD/32), wb>>>(W1 + (size_t)l*DD*FFD, W1TP + (size_t)l*FFD*DD, DD, FFD, FFD);
        wconv<<<dim3(DD/32, FFD/32), wb>>>(W2 + (size_t)l*FFD*DD, W2TP + (size_t)l*DD*FFD, FFD, DD, DD);
    }
    wconv<<<dim3(NPAD/32, DD/32), wb>>>(proj_w, projTP, DD, CVOC, NPAD);

    embed_kernel<<<MROWS, 256>>>(tokens, codes, tok_emb, audio_emb);

    for (int l = 0; l < NLAYER; l++) {
        gemm_mma<0,0,1><<<dim3(3*DD/128, MROWS/128), 256, GEMM_SMEM>>>(
            qkvP, hbP, WqkvTP + (size_t)l*3*DD*DD, b_qkv + (size_t)l*3*DD, MROWS, DD, 3*DD);
        attn_scores<<<dim3(SS/64, SS/64, BB*NH), 256>>>(qkvP);
        softmax_rows<<<BB*NH*SS, 256>>>();
        attn_pv<<<dim3(SS/64, BB*NH), 256>>>(qkvP);
        gemm_mma<0,0,1><<<dim3(DD/128, MROWS/128), 256, GEMM_SMEM>>>(
            tmpP, attnbP, WoTP + (size_t)l*DD*DD, b_o + (size_t)l*DD, MROWS, DD, DD);
        add_ln<<<MROWS, 256>>>(hP, hbP, hP, tmpP, ln1_w + l*DD, ln1_b + l*DD);
        gemm_mma<1,1,1><<<dim3(FFD/128, MROWS/128), 256, GEMM_SMEM>>>(
            ffbP, hbP, W1TP + (size_t)l*FFD*DD, b1 + (size_t)l*FFD, MROWS, DD, FFD);
        gemm_mma<0,0,1><<<dim3(DD/128, MROWS/128), 256, GEMM_SMEM>>>(
            tmpP, ffbP, W2TP + (size_t)l*DD*FFD, b2 + (size_t)l*DD, MROWS, FFD, DD);
        add_ln<<<MROWS, 256>>>(hP, hbP, hP, tmpP, ln2_w + l*DD, ln2_b + l*DD);
    }

    add_ln<<<MROWS, 256>>>(hP, nullptr, hP, nullptr, lnf_w, lnf_b);
    gather_rows<<<PROWS, 256>>>();
    gemm_mma<0,0,0><<<dim3(NPAD/128, PROWS/128), 256, GEMM_SMEM>>>(
        logitsP, xbP, projTP, nullptr, PROWS, DD, NPAD);
    nll_kernel<<<PROWS, 256>>>(codes);
    mean_kernel<<<1, 256>>>((float*)d_out);
}

// round 6
// speedup vs baseline: 7.6519x; 1.9334x over previous
#include <cuda_runtime.h>
#include <cuda_bf16.h>
#include <math.h>
#include <stdint.h>

#define BB 2
#define XL 256
#define CL 767
#define YL 768
#define SS 1024
#define DD 1024
#define FFD 4096
#define NLAYER 6
#define NH 16
#define DH 64
#define CVOC 1025
#define NPAD 1152
#define EOS_ID 1024
#define BOS_ID 1025
#define MROWS (BB*SS)
#define PROWS (BB*YL)

// ---------------- scratch (static device globals; no allocs) ----------------
__device__ float g_h[MROWS*DD];
__device__ __nv_bfloat16 g_hb[MROWS*DD];
__device__ __nv_bfloat16 g_qkvb[MROWS*3*DD];
__device__ __nv_bfloat16 g_attnb[MROWS*DD];
__device__ float g_tmp[MROWS*DD];
__device__ __nv_bfloat16 g_ffb[MROWS*FFD];
__device__ __nv_bfloat16 g_xb[PROWS*DD];
__device__ float g_logits[PROWS*NPAD];
__device__ float g_nll[PROWS];
__device__ __nv_bfloat16 g_WqkvT[NLAYER*3*DD*DD];
__device__ __nv_bfloat16 g_WoT[NLAYER*DD*DD];
__device__ __nv_bfloat16 g_W1T[NLAYER*FFD*DD];
__device__ __nv_bfloat16 g_W2T[NLAYER*DD*FFD];
__device__ __nv_bfloat16 g_projT[NPAD*DD];

// ---------------- helpers ----------------
__device__ __forceinline__ uint32_t smem_u32(const void* p) {
    uint32_t a;
    asm("{ .reg .u64 t; cvta.to.shared.u64 t, %1; cvt.u32.u64 %0, t; }" : "=r"(a) : "l"(p));
    return a;
}
__device__ __forceinline__ void cp16(void* smem_dst, const void* gsrc) {
    uint32_t s = smem_u32(smem_dst);
    asm volatile("cp.async.cg.shared.global [%0], [%1], 16;" :: "r"(s), "l"(gsrc));
}
__device__ __forceinline__ void cp_commit() { asm volatile("cp.async.commit_group;" ::: "memory"); }
__device__ __forceinline__ void cp_wait0()  { asm volatile("cp.async.wait_group 0;" ::: "memory"); }
__device__ __forceinline__ void cp_wait1()  { asm volatile("cp.async.wait_group 1;" ::: "memory"); }

__device__ __forceinline__ void ldm_x4(uint32_t* r, uint32_t addr) {
    asm volatile("ldmatrix.sync.aligned.m8n8.x4.shared.b16 {%0,%1,%2,%3}, [%4];"
        : "=r"(r[0]), "=r"(r[1]), "=r"(r[2]), "=r"(r[3]) : "r"(addr));
}
__device__ __forceinline__ void ldm_x4_t(uint32_t* r, uint32_t addr) {
    asm volatile("ldmatrix.sync.aligned.m8n8.x4.trans.shared.b16 {%0,%1,%2,%3}, [%4];"
        : "=r"(r[0]), "=r"(r[1]), "=r"(r[2]), "=r"(r[3]) : "r"(addr));
}
__device__ __forceinline__ void mma16816(float* c, const uint32_t* a, const uint32_t* b) {
    asm volatile("mma.sync.aligned.m16n8k16.row.col.f32.bf16.bf16.f32 "
        "{%0,%1,%2,%3}, {%4,%5,%6,%7}, {%8,%9}, {%0,%1,%2,%3};"
        : "+f"(c[0]), "+f"(c[1]), "+f"(c[2]), "+f"(c[3])
        : "r"(a[0]), "r"(a[1]), "r"(a[2]), "r"(a[3]), "r"(b[0]), "r"(b[1]));
}
__device__ __forceinline__ uint32_t pk(float x, float y) {
    __nv_bfloat162 p = __floats2bfloat162_rn(x, y);
    return *(uint32_t*)&p;
}

#define KCH 64
#define PADW 72
#define TILE_E (128*PADW)
#define GEMM_SMEM (4*TILE_E*2 + 512)

// ---------------- HMMA bf16 GEMM: C[M,N] = A[M,K] @ Wt[N,K]^T (+bias)(+relu) ----------------
template<int OUT_BF16, int RELU, int HAS_BIAS>
__global__ void __launch_bounds__(256) gemm_mma(void* __restrict__ Cv,
        const __nv_bfloat16* __restrict__ A, const __nv_bfloat16* __restrict__ Wt,
        const float* __restrict__ bias, int M, int K, int N) {
    extern __shared__ __nv_bfloat16 sm[];
    __nv_bfloat16* As = sm;
    __nv_bfloat16* Bs = sm + 2 * TILE_E;
    float* biasSm = (float*)(sm + 4 * TILE_E);

    int tid = threadIdx.x;
    int wid = tid >> 5, lane = tid & 31;
    int wm = wid >> 2, wn = wid & 3;
    int m0 = blockIdx.y * 128, n0 = blockIdx.x * 128;

    if (HAS_BIAS && tid < 128) biasSm[tid] = bias[n0 + tid];

    const size_t rsA = (size_t)K;
    const __nv_bfloat16* gA = A + (size_t)m0 * K;
    const __nv_bfloat16* gB = Wt + (size_t)n0 * K;

    float acc[4][4][4];
#pragma unroll
    for (int i = 0; i < 4; i++)
#pragma unroll
        for (int j = 0; j < 4; j++)
#pragma unroll
            for (int q = 0; q < 4; q++) acc[i][j][q] = 0.f;

    const int nch = K / KCH;
#pragma unroll
    for (int i = 0; i < 4; i++) {
        int c = tid + 256 * i;
        int row = c >> 3, cc = c & 7;
        cp16(As + row * PADW + cc * 8, gA + (size_t)row * rsA + cc * 8);
        cp16(Bs + row * PADW + cc * 8, gB + (size_t)row * rsA + cc * 8);
    }
    cp_commit();

    int a_r = (lane & 7) + ((lane >> 3) & 1) * 8;
    int a_ch = (lane >> 4) * 8;
    int b_r = (lane & 7) + (lane >> 4) * 8;
    int b_ch = ((lane >> 3) & 1) * 8;

    for (int ic = 0; ic < nch; ic++) {
        int buf = ic & 1;
        cp_wait0();
        __syncthreads();
        if (ic + 1 < nch) {
            const __nv_bfloat16* gA1 = gA + (size_t)(ic + 1) * KCH;
            const __nv_bfloat16* gB1 = gB + (size_t)(ic + 1) * KCH;
            __nv_bfloat16* dA = As + (buf ^ 1) * TILE_E;
            __nv_bfloat16* dB = Bs + (buf ^ 1) * TILE_E;
#pragma unroll
            for (int i = 0; i < 4; i++) {
                int c = tid + 256 * i;
                int row = c >> 3, cc = c & 7;
                cp16(dA + row * PADW + cc * 8, gA1 + (size_t)row * rsA + cc * 8);
                cp16(dB + row * PADW + cc * 8, gB1 + (size_t)row * rsA + cc * 8);
            }
            cp_commit();
        }

        const __nv_bfloat16* As_ = As + buf * TILE_E;
        const __nv_bfloat16* Bs_ = Bs + buf * TILE_E;
#pragma unroll
        for (int ks = 0; ks < 4; ks++) {
            int koff = ks * 16;
            uint32_t a[4][4], b[2][4];
#pragma unroll
            for (int mi = 0; mi < 4; mi++)
                ldm_x4(a[mi], smem_u32(As_ + (size_t)(wm * 64 + mi * 16 + a_r) * PADW + koff + a_ch));
#pragma unroll
            for (int ni2 = 0; ni2 < 2; ni2++)
                ldm_x4(b[ni2], smem_u32(Bs_ + (size_t)(wn * 32 + ni2 * 16 + b_r) * PADW + koff + b_ch));
#pragma unroll
            for (int mi = 0; mi < 4; mi++)
#pragma unroll
                for (int ni = 0; ni < 4; ni++)
                    mma16816(acc[mi][ni], a[mi], b[ni >> 1] + (ni & 1) * 2);
        }
        __syncthreads();
    }

    int rg = lane >> 2, cg = (lane & 3) * 2;
#pragma unroll
    for (int mi = 0; mi < 4; mi++) {
#pragma unroll
        for (int ni = 0; ni < 4; ni++) {
            int colL = wn * 32 + ni * 8 + cg;
            int col = n0 + colL;
            float b0 = HAS_BIAS ? biasSm[colL] : 0.f;
            float b1 = HAS_BIAS ? biasSm[colL + 1] : 0.f;
#pragma unroll
            for (int rh = 0; rh < 2; rh++) {
                int row = m0 + wm * 64 + mi * 16 + rg + rh * 8;
                float v0 = acc[mi][ni][rh * 2 + 0] + b0;
                float v1 = acc[mi][ni][rh * 2 + 1] + b1;
                if (RELU) { v0 = fmaxf(v0, 0.f); v1 = fmaxf(v1, 0.f); }
                if (OUT_BF16) {
                    __nv_bfloat162 p = __floats2bfloat162_rn(v0, v1);
                    *(__nv_bfloat162*)((__nv_bfloat16*)Cv + (size_t)row * N + col) = p;
                } else {
                    *(float2*)((float*)Cv + (size_t)row * N + col) = make_float2(v0, v1);
                }
            }
        }
    }
}

// ---------------- fused flash attention ----------------
// grid (SS/128, BB*NH), block 256 (8 warps x 16 query rows)
#define FLASH_SMEM ((128*PADW + 2*64*PADW + 2*64*PADW) * 2)
__global__ void __launch_bounds__(256) flash_attn(const __nv_bfloat16* __restrict__ qkvb) {
    extern __shared__ __nv_bfloat16 fsm[];
    __nv_bfloat16* Qs = fsm;                          // [128][72]
    __nv_bfloat16* Ks = fsm + 128 * PADW;             // [2][64][72]
    __nv_bfloat16* Vs = fsm + 128 * PADW + 2 * 64 * PADW;

    int bh = blockIdx.y;
    int b = bh / NH, h = bh % NH;
    int i0 = blockIdx.x * 128;
    int ntile = ((i0 < XL) ? XL : (i0 + 128)) / 64;

    int tid = threadIdx.x, w = tid >> 5, lane = tid & 31;
    const __nv_bfloat16* base = qkvb + (size_t)(b * SS) * 3 * DD + h * DH;

    // prologue: Q + K0 + V0
#pragma unroll
    for (int i = 0; i < 4; i++) {
        int c = tid + 256 * i;
        int row = c >> 3, cc = c & 7;
        cp16(Qs + row * PADW + cc * 8, base + (size_t)(i0 + row) * 3 * DD + cc * 8);
    }
#pragma unroll
    for (int i = 0; i < 2; i++) {
        int c = tid + 256 * i;
        int row = c >> 3, cc = c & 7;
        cp16(Ks + row * PADW + cc * 8, base + (size_t)row * 3 * DD + DD + cc * 8);
        cp16(Vs + row * PADW + cc * 8, base + (size_t)row * 3 * DD + 2 * DD + cc * 8);
    }
    cp_commit();

    float m0 = -1e30f, m1 = -1e30f, l0 = 0.f, l1 = 0.f;
    float o[8][4];
#pragma unroll
    for (int dt = 0; dt < 8; dt++)
#pragma unroll
        for (int q = 0; q < 4; q++) o[dt][q] = 0.f;

    int a_r = (lane & 7) + ((lane >> 3) & 1) * 8;
    int a_ch = (lane >> 4) * 8;
    int b_r = (lane & 7) + (lane >> 4) * 8;
    int b_ch = ((lane >> 3) & 1) * 8;
    int r0g = i0 + w * 16 + (lane >> 2);

    for (int t = 0; t < ntile; t++) {
        int buf = t & 1;
        if (t + 1 < ntile) {
            int j1 = (t + 1) * 64, nb = (t + 1) & 1;
#pragma unroll
            for (int i = 0; i < 2; i++) {
                int c = tid + 256 * i;
                int row = c >> 3, cc = c & 7;
                cp16(Ks + nb * 64 * PADW + row * PADW + cc * 8, base + (size_t)(j1 + row) * 3 * DD + DD + cc * 8);
                cp16(Vs + nb * 64 * PADW + row * PADW + cc * 8, base + (size_t)(j1 + row) * 3 * DD + 2 * DD + cc * 8);
            }
            cp_commit();
            cp_wait1();
        } else {
            cp_wait0();
        }
        __syncthreads();
        const __nv_bfloat16* K_ = Ks + buf * 64 * PADW;
        const __nv_bfloat16* V_ = Vs + buf * 64 * PADW;

        // S = Q K^T (128x64 per block, 16x64 per warp)
        float s[8][4];
#pragma unroll
        for (int nt = 0; nt < 8; nt++)
#pragma unroll
            for (int q = 0; q < 4; q++) s[nt][q] = 0.f;
#pragma unroll
        for (int kd = 0; kd < 4; kd++) {
            uint32_t a[4];
            ldm_x4(a, smem_u32(Qs + (size_t)(w * 16 + a_r) * PADW + kd * 16 + a_ch));
            uint32_t bb[4][4];
#pragma unroll
            for (int nj = 0; nj < 4; nj++)
                ldm_x4(bb[nj], smem_u32(K_ + (size_t)(nj * 16 + b_r) * PADW + kd * 16 + b_ch));
#pragma unroll
            for (int nt = 0; nt < 8; nt++)
                mma16816(s[nt], a, bb[nt >> 1] + (nt & 1) * 2);
        }

        const float SC = 0.125f * 1.44269504f;
        int j0 = t * 64;
        if (i0 >= XL && j0 + 63 >= i0) {
#pragma unroll
            for (int nt = 0; nt < 8; nt++) {
                int j = j0 + nt * 8 + (lane & 3) * 2;
                s[nt][0] = (j     <= r0g)     ? s[nt][0] * SC : -1e30f;
                s[nt][1] = (j + 1 <= r0g)     ? s[nt][1] * SC : -1e30f;
                s[nt][2] = (j     <= r0g + 8) ? s[nt][2] * SC : -1e30f;
                s[nt][3] = (j + 1 <= r0g + 8) ? s[nt][3] * SC : -1e30f;
            }
        } else {
#pragma unroll
            for (int nt = 0; nt < 8; nt++)
#pragma unroll
                for (int q = 0; q < 4; q++) s[nt][q] *= SC;
        }

        // online softmax
        float t0 = -1e30f, t1 = -1e30f;
#pragma unroll
        for (int nt = 0; nt < 8; nt++) {
            t0 = fmaxf(t0, fmaxf(s[nt][0], s[nt][1]));
            t1 = fmaxf(t1, fmaxf(s[nt][2], s[nt][3]));
        }
        t0 = fmaxf(t0, __shfl_xor_sync(0xffffffff, t0, 1));
        t0 = fmaxf(t0, __shfl_xor_sync(0xffffffff, t0, 2));
        t1 = fmaxf(t1, __shfl_xor_sync(0xffffffff, t1, 1));
        t1 = fmaxf(t1, __shfl_xor_sync(0xffffffff, t1, 2));
        float mn0 = fmaxf(m0, t0), mn1 = fmaxf(m1, t1);
        float al0 = exp2f(m0 - mn0), al1 = exp2f(m1 - mn1);
        m0 = mn0; m1 = mn1;
        float rs0 = 0.f, rs1 = 0.f;
#pragma unroll
        for (int nt = 0; nt < 8; nt++) {
            s[nt][0] = exp2f(s[nt][0] - m0); rs0 += s[nt][0];
            s[nt][1] = exp2f(s[nt][1] - m0); rs0 += s[nt][1];
            s[nt][2] = exp2f(s[nt][2] - m1); rs1 += s[nt][2];
            s[nt][3] = exp2f(s[nt][3] - m1); rs1 += s[nt][3];
        }
        rs0 += __shfl_xor_sync(0xffffffff, rs0, 1);
        rs0 += __shfl_xor_sync(0xffffffff, rs0, 2);
        rs1 += __shfl_xor_sync(0xffffffff, rs1, 1);
        rs1 += __shfl_xor_sync(0xffffffff, rs1, 2);
        l0 = l0 * al0 + rs0; l1 = l1 * al1 + rs1;
#pragma unroll
        for (int dt = 0; dt < 8; dt++) {
            o[dt][0] *= al0; o[dt][1] *= al0;
            o[dt][2] *= al1; o[dt][3] *= al1;
        }

        // pack P fragments
        uint32_t pa[4][4];
#pragma unroll
        for (int kt = 0; kt < 4; kt++) {
            pa[kt][0] = pk(s[2 * kt][0], s[2 * kt][1]);
            pa[kt][1] = pk(s[2 * kt][2], s[2 * kt][3]);
            pa[kt][2] = pk(s[2 * kt + 1][0], s[2 * kt + 1][1]);
            pa[kt][3] = pk(s[2 * kt + 1][2], s[2 * kt + 1][3]);
        }

        // O += P V
#pragma unroll
        for (int kt = 0; kt < 4; kt++) {
#pragma unroll
            for (int dv = 0; dv < 4; dv++) {
                uint32_t vb[4];
                ldm_x4_t(vb, smem_u32(V_ + (size_t)(kt * 16 + (lane & 15)) * PADW + dv * 16 + (lane >> 4) * 8));
                mma16816(o[dv * 2], pa[kt], vb);
                mma16816(o[dv * 2 + 1], pa[kt], vb + 2);
            }
        }
        __syncthreads();
    }

    float inv0 = 1.f / l0, inv1 = 1.f / l1;
#pragma unroll
    for (int dt = 0; dt < 8; dt++) {
        int cols = h * DH + dt * 8 + (lane & 3) * 2;
        __nv_bfloat162 p0 = __floats2bfloat162_rn(o[dt][0] * inv0, o[dt][1] * inv0);
        __nv_bfloat162 p1 = __floats2bfloat162_rn(o[dt][2] * inv1, o[dt][3] * inv1);
        *(__nv_bfloat162*)(g_attnb + (size_t)(b * SS + r0g) * DD + cols) = p0;
        *(__nv_bfloat162*)(g_attnb + (size_t)(b * SS + r0g + 8) * DD + cols) = p1;
    }
}

// ---------------- weight fp32[K,N] -> bf16 transposed [Nt,K] ----------------
__global__ void wconv(const float* __restrict__ W, __nv_bfloat16* __restrict__ Wt,
                      int K, int N, int Nt) {
    __shared__ float t[32][33];
    int n0 = blockIdx.x * 32, k0 = blockIdx.y * 32;
    int tx = threadIdx.x, ty = threadIdx.y;
#pragma unroll
    for (int j = 0; j < 32; j += 8) {
        int n = n0 + tx, k = k0 + ty + j;
        t[ty + j][tx] = (n < N) ? W[(size_t)k * N + n] : 0.f;
    }
    __syncthreads();
#pragma unroll
    for (int j = 0; j < 32; j += 8) {
        int n = n0 + ty + j, k = k0 + tx;
        if (n < Nt) Wt[(size_t)n * K + k] = __float2bfloat16(t[tx][ty + j]);
    }
}

// ---------------- block reductions ----------------
__device__ __forceinline__ float blk_reduce_max(float v, float* red) {
    int t = threadIdx.x;
    red[t] = v; __syncthreads();
    for (int s = 128; s > 0; s >>= 1) { if (t < s) red[t] = fmaxf(red[t], red[t + s]); __syncthreads(); }
    float r = red[0]; __syncthreads();
    return r;
}
__device__ __forceinline__ float blk_reduce_sum(float v, float* red) {
    int t = threadIdx.x;
    red[t] = v; __syncthreads();
    for (int s = 128; s > 0; s >>= 1) { if (t < s) red[t] += red[t + s]; __syncthreads(); }
    float r = red[0]; __syncthreads();
    return r;
}

// ---------------- embedding + sinusoidal PE ----------------
__global__ void embed_kernel(const int* __restrict__ tokens, const int* __restrict__ codes,
                             const float* __restrict__ tok_emb, const float* __restrict__ audio_emb) {
    int row = blockIdx.x;
    int b = row / SS, s = row % SS;
    const float* src; int pos;
    if (s < XL) { src = tok_emb + (size_t)tokens[b*XL + s] * DD; pos = s; }
    else {
        int sy = s - XL;
        int id = (sy == 0) ? BOS_ID : codes[b*CL + sy - 1];
        src = audio_emb + (size_t)id * DD; pos = sy;
    }
    float* dst = g_h + (size_t)row * DD;
    __nv_bfloat16* dstb = g_hb + (size_t)row * DD;
    const float kinv = 9.210340371976184f / (float)DD;
    for (int d = threadIdx.x; d < DD; d += blockDim.x) {
        float freq = expf(-(float)(d & ~1) * kinv);
        float ang = (float)pos * freq;
        float pe = (d & 1) ? cosf(ang) : sinf(ang);
        float v = src[d] + pe;
        dst[d] = v;
        dstb[d] = __float2bfloat16(v);
    }
}

// ---------------- dst = LayerNorm(x + add), also bf16 copy ----------------
__global__ void add_ln(float* __restrict__ dst, __nv_bfloat16* __restrict__ dstb,
                       const float* __restrict__ x, const float* __restrict__ addv,
                       const float* __restrict__ w, const float* __restrict__ bvec) {
    __shared__ float buf[DD];
    __shared__ float red[256];
    int row = blockIdx.x;
    int tid = threadIdx.x;
    const float* xr = x + (size_t)row * DD;
    const float* ar = addv ? (addv + (size_t)row * DD) : nullptr;

    float lsum = 0.f;
    for (int d = tid; d < DD; d += 256) {
        float v = xr[d] + (ar ? ar[d] : 0.f);
        buf[d] = v; lsum += v;
    }
    float mu = blk_reduce_sum(lsum, red) * (1.f / DD);
    float lsq = 0.f;
    for (int d = tid; d < DD; d += 256) { float t = buf[d] - mu; lsq += t * t; }
    float var = blk_reduce_sum(lsq, red) * (1.f / DD);
    float rstd = rsqrtf(var + 1e-5f);

    float* dr = dst + (size_t)row * DD;
    __nv_bfloat16* db = dstb ? (dstb + (size_t)row * DD) : nullptr;
    for (int d = tid; d < DD; d += 256) {
        float v = (buf[d] - mu) * rstd * w[d] + bvec[d];
        dr[d] = v;
        if (db) db[d] = __float2bfloat16(v);
    }
}

// ---------------- gather audio rows (bf16) ----------------
__global__ void gather_rows() {
    int m = blockIdx.x;
    int b = m / YL, t = m % YL;
    const float* src = g_h + (size_t)(b*SS + XL + t) * DD;
    __nv_bfloat16* dst = g_xb + (size_t)m * DD;
    for (int d = threadIdx.x; d < DD; d += blockDim.x) dst[d] = __float2bfloat16(src[d]);
}

// ---------------- per-row NLL ----------------
__global__ void nll_kernel(const int* __restrict__ codes) {
    __shared__ float red[256];
    int m = blockIdx.x;
    int b = m / YL, t = m % YL;
    const float* row = g_logits + (size_t)m * NPAD;
    int tid = threadIdx.x;

    float lmax = -1e30f;
    for (int j = tid; j < CVOC; j += 256) lmax = fmaxf(lmax, row[j]);
    lmax = blk_reduce_max(lmax, red);
    float lsum = 0.f;
    for (int j = tid; j < CVOC; j += 256) lsum += expf(row[j] - lmax);
    lsum = blk_reduce_sum(lsum, red);
    if (tid == 0) {
        int tgt = (t < CL) ? codes[b*CL + t] : EOS_ID;
        g_nll[m] = lmax + logf(lsum) - row[tgt];
    }
}

__global__ void mean_kernel(float* __restrict__ out) {
    __shared__ float red[256];
    int tid = threadIdx.x;
    float s = 0.f;
    for (int i = tid; i < PROWS; i += 256) s += g_nll[i];
    s = blk_reduce_sum(s, red);
    if (tid == 0) out[0] = s / (float)PROWS;
}

// ---------------- launch ----------------
extern "C" void kernel_launch(void* const* d_in, const int* in_sizes, int n_in,
                              void* d_out, int out_size) {
    const int*   tokens    = (const int*)d_in[0];
    const int*   codes     = (const int*)d_in[1];
    const float* tok_emb   = (const float*)d_in[2];
    const float* audio_emb = (const float*)d_in[3];
    const float* Wqkv      = (const float*)d_in[4];
    const float* b_qkv     = (const float*)d_in[5];
    const float* Wo        = (const float*)d_in[6];
    const float* b_o       = (const float*)d_in[7];
    const float* W1        = (const float*)d_in[8];
    const float* b1        = (const float*)d_in[9];
    const float* W2        = (const float*)d_in[10];
    const float* b2        = (const float*)d_in[11];
    const float* ln1_w     = (const float*)d_in[12];
    const float* ln1_b     = (const float*)d_in[13];
    const float* ln2_w     = (const float*)d_in[14];
    const float* ln2_b     = (const float*)d_in[15];
    const float* lnf_w     = (const float*)d_in[16];
    const float* lnf_b     = (const float*)d_in[17];
    const float* proj_w    = (const float*)d_in[18];

    float *hP, *tmpP, *logitsP;
    __nv_bfloat16 *hbP, *qkvbP, *attnbP, *ffbP, *xbP, *WqkvTP, *WoTP, *W1TP, *W2TP, *projTP;
    cudaGetSymbolAddress((void**)&hP, g_h);
    cudaGetSymbolAddress((void**)&hbP, g_hb);
    cudaGetSymbolAddress((void**)&qkvbP, g_qkvb);
    cudaGetSymbolAddress((void**)&attnbP, g_attnb);
    cudaGetSymbolAddress((void**)&tmpP, g_tmp);
    cudaGetSymbolAddress((void**)&ffbP, g_ffb);
    cudaGetSymbolAddress((void**)&xbP, g_xb);
    cudaGetSymbolAddress((void**)&logitsP, g_logits);
    cudaGetSymbolAddress((void**)&WqkvTP, g_WqkvT);
    cudaGetSymbolAddress((void**)&WoTP, g_WoT);
    cudaGetSymbolAddress((void**)&W1TP, g_W1T);
    cudaGetSymbolAddress((void**)&W2TP, g_W2T);
    cudaGetSymbolAddress((void**)&projTP, g_projT);

    cudaFuncSetAttribute(gemm_mma<0,0,1>, cudaFuncAttributeMaxDynamicSharedMemorySize, GEMM_SMEM);
    cudaFuncSetAttribute(gemm_mma<1,0,1>, cudaFuncAttributeMaxDynamicSharedMemorySize, GEMM_SMEM);
    cudaFuncSetAttribute(gemm_mma<1,1,1>, cudaFuncAttributeMaxDynamicSharedMemorySize, GEMM_SMEM);
    cudaFuncSetAttribute(gemm_mma<0,0,0>, cudaFuncAttributeMaxDynamicSharedMemorySize, GEMM_SMEM);
    cudaFuncSetAttribute(flash_attn, cudaFuncAttributeMaxDynamicSharedMemorySize, FLASH_SMEM);

    dim3 wb(32, 8);
    for (int l = 0; l < NLAYER; l++) {
        wconv<<<dim3(3*DD/32, DD/32), wb>>>(Wqkv + (size_t)l*DD*3*DD, WqkvTP + (size_t)l*3*DD*DD, DD, 3*DD, 3*DD);
        wconv<<<dim3(DD/32, DD/32), wb>>>(Wo + (size_t)l*DD*DD, WoTP + (size_t)l*DD*DD, DD, DD, DD);
        wconv<<<dim3(FFD/32, DD/32), wb>>>(W1 + (size_t)l*DD*FFD, W1TP + (size_t)l*FFD*DD, DD, FFD, FFD);
        wconv<<<dim3(DD/32, FFD/32), wb>>>(W2 + (size_t)l*FFD*DD, W2TP + (size_t)l*DD*FFD, FFD, DD, DD);
    }
    wconv<<<dim3(NPAD/32, DD/32), wb>>>(proj_w, projTP, DD, CVOC, NPAD);

    embed_kernel<<<MROWS, 256>>>(tokens, codes, tok_emb, audio_emb);

    for (int l = 0; l < NLAYER; l++) {
        gemm_mma<1,0,1><<<dim3(3*DD/128, MROWS/128), 256, GEMM_SMEM>>>(
            qkvbP, hbP, WqkvTP + (size_t)l*3*DD*DD, b_qkv + (size_t)l*3*DD, MROWS, DD, 3*DD);
        flash_attn<<<dim3(SS/128, BB*NH), 256, FLASH_SMEM>>>(qkvbP);
        gemm_mma<0,0,1><<<dim3(DD/128, MROWS/128), 256, GEMM_SMEM>>>(
            tmpP, attnbP, WoTP + (size_t)l*DD*DD, b_o + (size_t)l*DD, MROWS, DD, DD);
        add_ln<<<MROWS, 256>>>(hP, hbP, hP, tmpP, ln1_w + l*DD, ln1_b + l*DD);
        gemm_mma<1,1,1><<<dim3(FFD/128, MROWS/128), 256, GEMM_SMEM>>>(
            ffbP, hbP, W1TP + (size_t)l*FFD*DD, b1 + (size_t)l*FFD, MROWS, DD, FFD);
        gemm_mma<0,0,1><<<dim3(DD/128, MROWS/128), 256, GEMM_SMEM>>>(
            tmpP, ffbP, W2TP + (size_t)l*DD*FFD, b2 + (size_t)l*DD, MROWS, FFD, DD);
        add_ln<<<MROWS, 256>>>(hP, hbP, hP, tmpP, ln2_w + l*DD, ln2_b + l*DD);
    }

    add_ln<<<MROWS, 256>>>(hP, nullptr, hP, nullptr, lnf_w, lnf_b);
    gather_rows<<<PROWS, 256>>>();
    gemm_mma<0,0,0><<<dim3(NPAD/128, PROWS/128), 256, GEMM_SMEM>>>(
        logitsP, xbP, projTP, nullptr, PROWS, DD, NPAD);
    nll_kernel<<<PROWS, 256>>>(codes);
    mean_kernel<<<1, 256>>>((float*)d_out);
}

// round 7
// speedup vs baseline: 7.9662x; 1.0411x over previous
#include <cuda_runtime.h>
#include <cuda_bf16.h>
#include <math.h>
#include <stdint.h>

#define BB 2
#define XL 256
#define CL 767
#define YL 768
#define SS 1024
#define DD 1024
#define FFD 4096
#define NLAYER 6
#define NH 16
#define DH 64
#define CVOC 1025
#define NPAD 1152
#define EOS_ID 1024
#define BOS_ID 1025
#define MROWS (BB*SS)
#define PROWS (BB*YL)

// ---------------- scratch (static device globals; no allocs) ----------------
__device__ float g_h[MROWS*DD];
__device__ __nv_bfloat16 g_hb[MROWS*DD];
__device__ __nv_bfloat16 g_qkvb[MROWS*3*DD];
__device__ __nv_bfloat16 g_attnb[MROWS*DD];
__device__ float g_tmp[2*MROWS*DD];                 // split-K partials
__device__ __nv_bfloat16 g_ffb[MROWS*FFD];
__device__ __nv_bfloat16 g_xb[PROWS*DD];
__device__ float g_logits[2*PROWS*NPAD];            // split-K partials
__device__ float g_nll[PROWS];
// bf16 K-major weights [K,N] (no transpose)
__device__ __nv_bfloat16 g_Wqkv[NLAYER*DD*3*DD];
__device__ __nv_bfloat16 g_Wo[NLAYER*DD*DD];
__device__ __nv_bfloat16 g_W1[NLAYER*DD*FFD];
__device__ __nv_bfloat16 g_W2[NLAYER*FFD*DD];
__device__ __nv_bfloat16 g_proj[DD*NPAD];

// ---------------- helpers ----------------
__device__ __forceinline__ uint32_t smem_u32(const void* p) {
    uint32_t a;
    asm("{ .reg .u64 t; cvta.to.shared.u64 t, %1; cvt.u32.u64 %0, t; }" : "=r"(a) : "l"(p));
    return a;
}
__device__ __forceinline__ void cp16(void* smem_dst, const void* gsrc) {
    uint32_t s = smem_u32(smem_dst);
    asm volatile("cp.async.cg.shared.global [%0], [%1], 16;" :: "r"(s), "l"(gsrc));
}
__device__ __forceinline__ void cp_commit() { asm volatile("cp.async.commit_group;" ::: "memory"); }
__device__ __forceinline__ void cp_wait0()  { asm volatile("cp.async.wait_group 0;" ::: "memory"); }
__device__ __forceinline__ void cp_wait1()  { asm volatile("cp.async.wait_group 1;" ::: "memory"); }

__device__ __forceinline__ void ldm_x4(uint32_t* r, uint32_t addr) {
    asm volatile("ldmatrix.sync.aligned.m8n8.x4.shared.b16 {%0,%1,%2,%3}, [%4];"
        : "=r"(r[0]), "=r"(r[1]), "=r"(r[2]), "=r"(r[3]) : "r"(addr));
}
__device__ __forceinline__ void ldm_x4_t(uint32_t* r, uint32_t addr) {
    asm volatile("ldmatrix.sync.aligned.m8n8.x4.trans.shared.b16 {%0,%1,%2,%3}, [%4];"
        : "=r"(r[0]), "=r"(r[1]), "=r"(r[2]), "=r"(r[3]) : "r"(addr));
}
__device__ __forceinline__ void mma16816(float* c, const uint32_t* a, const uint32_t* b) {
    asm volatile("mma.sync.aligned.m16n8k16.row.col.f32.bf16.bf16.f32 "
        "{%0,%1,%2,%3}, {%4,%5,%6,%7}, {%8,%9}, {%0,%1,%2,%3};"
        : "+f"(c[0]), "+f"(c[1]), "+f"(c[2]), "+f"(c[3])
        : "r"(a[0]), "r"(a[1]), "r"(a[2]), "r"(a[3]), "r"(b[0]), "r"(b[1]));
}
__device__ __forceinline__ uint32_t pk(float x, float y) {
    __nv_bfloat162 p = __floats2bfloat162_rn(x, y);
    return *(uint32_t*)&p;
}

#define KCH 64
#define PADW 72                    // A-tile row pad (bf16 elems)
#define PADB 136                   // B-tile row pad (bf16 elems, 272B -> conflict-free trans ldm)
#define ATILE_E (128*PADW)
#define BTILE_E (64*PADB)
#define GEMM_SMEM ((2*ATILE_E + 2*BTILE_E)*2 + 512)

// ---------------- HMMA bf16 GEMM: C[M,N] = A[M,K] @ W[K,N] (+bias)(+relu), optional split-K ----------------
// grid (N/128, M/128, SPLITK), block 256 (8 warps: 2 M x 4 N; warp tile 64x32)
template<int OUT_BF16, int RELU, int HAS_BIAS, int SPLITK>
__global__ void __launch_bounds__(256) gemm_mma(void* __restrict__ Cv,
        const __nv_bfloat16* __restrict__ A, const __nv_bfloat16* __restrict__ W,
        const float* __restrict__ bias, int M, int K, int N) {
    extern __shared__ __nv_bfloat16 sm[];
    __nv_bfloat16* As = sm;                       // [2][128][PADW]
    __nv_bfloat16* Bs = sm + 2 * ATILE_E;         // [2][64][PADB]
    float* biasSm = (float*)(sm + 2 * ATILE_E + 2 * BTILE_E);

    int tid = threadIdx.x;
    int wid = tid >> 5, lane = tid & 31;
    int wm = wid >> 2, wn = wid & 3;
    int m0 = blockIdx.y * 128, n0 = blockIdx.x * 128;
    int kLen = K / SPLITK;
    int kStart = blockIdx.z * kLen;

    if (HAS_BIAS && tid < 128) biasSm[tid] = bias[n0 + tid];

    const __nv_bfloat16* gA = A + (size_t)m0 * K + kStart;
    const __nv_bfloat16* gB = W + (size_t)kStart * N + n0;

    float acc[4][4][4];
#pragma unroll
    for (int i = 0; i < 4; i++)
#pragma unroll
        for (int j = 0; j < 4; j++)
#pragma unroll
            for (int q = 0; q < 4; q++) acc[i][j][q] = 0.f;

    const int nch = kLen / KCH;
    // prologue chunk 0
#pragma unroll
    for (int i = 0; i < 4; i++) {
        int c = tid + 256 * i;
        int ar = c >> 3, ap = c & 7;
        cp16(As + ar * PADW + ap * 8, gA + (size_t)ar * K + ap * 8);
        int br = c >> 4, bp = c & 15;
        cp16(Bs + br * PADB + bp * 8, gB + (size_t)br * N + bp * 8);
    }
    cp_commit();

    int a_r = (lane & 7) + ((lane >> 3) & 1) * 8;
    int a_ch = (lane >> 4) * 8;

    for (int ic = 0; ic < nch; ic++) {
        int buf = ic & 1;
        cp_wait0();
        __syncthreads();
        if (ic + 1 < nch) {
            const __nv_bfloat16* gA1 = gA + (size_t)(ic + 1) * KCH;
            const __nv_bfloat16* gB1 = gB + (size_t)(ic + 1) * KCH * N;
            __nv_bfloat16* dA = As + (buf ^ 1) * ATILE_E;
            __nv_bfloat16* dB = Bs + (buf ^ 1) * BTILE_E;
#pragma unroll
            for (int i = 0; i < 4; i++) {
                int c = tid + 256 * i;
                int ar = c >> 3, ap = c & 7;
                cp16(dA + ar * PADW + ap * 8, gA1 + (size_t)ar * K + ap * 8);
                int br = c >> 4, bp = c & 15;
                cp16(dB + br * PADB + bp * 8, gB1 + (size_t)br * N + bp * 8);
            }
            cp_commit();
        }

        const __nv_bfloat16* As_ = As + buf * ATILE_E;
        const __nv_bfloat16* Bs_ = Bs + buf * BTILE_E;
#pragma unroll
        for (int ks = 0; ks < 4; ks++) {
            uint32_t a[4][4], b[2][4];
#pragma unroll
            for (int mi = 0; mi < 4; mi++)
                ldm_x4(a[mi], smem_u32(As_ + (size_t)(wm * 64 + mi * 16 + a_r) * PADW + ks * 16 + a_ch));
#pragma unroll
            for (int ni2 = 0; ni2 < 2; ni2++)
                ldm_x4_t(b[ni2], smem_u32(Bs_ + (size_t)(ks * 16 + (lane & 15)) * PADB + wn * 32 + ni2 * 16 + (lane >> 4) * 8));
#pragma unroll
            for (int mi = 0; mi < 4; mi++)
#pragma unroll
                for (int ni = 0; ni < 4; ni++)
                    mma16816(acc[mi][ni], a[mi], b[ni >> 1] + (ni & 1) * 2);
        }
        __syncthreads();
    }

    float* Cf = (float*)Cv + (SPLITK > 1 ? (size_t)blockIdx.z * M * N : 0);
    int rg = lane >> 2, cg = (lane & 3) * 2;
#pragma unroll
    for (int mi = 0; mi < 4; mi++) {
#pragma unroll
        for (int ni = 0; ni < 4; ni++) {
            int colL = wn * 32 + ni * 8 + cg;
            int col = n0 + colL;
            float b0 = HAS_BIAS ? biasSm[colL] : 0.f;
            float b1 = HAS_BIAS ? biasSm[colL + 1] : 0.f;
#pragma unroll
            for (int rh = 0; rh < 2; rh++) {
                int row = m0 + wm * 64 + mi * 16 + rg + rh * 8;
                float v0 = acc[mi][ni][rh * 2 + 0] + b0;
                float v1 = acc[mi][ni][rh * 2 + 1] + b1;
                if (RELU) { v0 = fmaxf(v0, 0.f); v1 = fmaxf(v1, 0.f); }
                if (OUT_BF16) {
                    __nv_bfloat162 p = __floats2bfloat162_rn(v0, v1);
                    *(__nv_bfloat162*)((__nv_bfloat16*)Cv + (size_t)row * N + col) = p;
                } else {
                    *(float2*)(Cf + (size_t)row * N + col) = make_float2(v0, v1);
                }
            }
        }
    }
}

// ---------------- fused flash attention ----------------
#define FLASH_SMEM ((128*PADW + 2*64*PADW + 2*64*PADW) * 2)
__global__ void __launch_bounds__(256) flash_attn(const __nv_bfloat16* __restrict__ qkvb) {
    extern __shared__ __nv_bfloat16 fsm[];
    __nv_bfloat16* Qs = fsm;
    __nv_bfloat16* Ks = fsm + 128 * PADW;
    __nv_bfloat16* Vs = fsm + 128 * PADW + 2 * 64 * PADW;

    int bh = blockIdx.y;
    int b = bh / NH, h = bh % NH;
    int i0 = blockIdx.x * 128;
    int ntile = ((i0 < XL) ? XL : (i0 + 128)) / 64;

    int tid = threadIdx.x, w = tid >> 5, lane = tid & 31;
    const __nv_bfloat16* base = qkvb + (size_t)(b * SS) * 3 * DD + h * DH;

#pragma unroll
    for (int i = 0; i < 4; i++) {
        int c = tid + 256 * i;
        int row = c >> 3, cc = c & 7;
        cp16(Qs + row * PADW + cc * 8, base + (size_t)(i0 + row) * 3 * DD + cc * 8);
    }
#pragma unroll
    for (int i = 0; i < 2; i++) {
        int c = tid + 256 * i;
        int row = c >> 3, cc = c & 7;
        cp16(Ks + row * PADW + cc * 8, base + (size_t)row * 3 * DD + DD + cc * 8);
        cp16(Vs + row * PADW + cc * 8, base + (size_t)row * 3 * DD + 2 * DD + cc * 8);
    }
    cp_commit();

    float m0 = -1e30f, m1 = -1e30f, l0 = 0.f, l1 = 0.f;
    float o[8][4];
#pragma unroll
    for (int dt = 0; dt < 8; dt++)
#pragma unroll
        for (int q = 0; q < 4; q++) o[dt][q] = 0.f;

    int a_r = (lane & 7) + ((lane >> 3) & 1) * 8;
    int a_ch = (lane >> 4) * 8;
    int b_r = (lane & 7) + (lane >> 4) * 8;
    int b_ch = ((lane >> 3) & 1) * 8;
    int r0g = i0 + w * 16 + (lane >> 2);

    for (int t = 0; t < ntile; t++) {
        int buf = t & 1;
        if (t + 1 < ntile) {
            int j1 = (t + 1) * 64, nb = (t + 1) & 1;
#pragma unroll
            for (int i = 0; i < 2; i++) {
                int c = tid + 256 * i;
                int row = c >> 3, cc = c & 7;
                cp16(Ks + nb * 64 * PADW + row * PADW + cc * 8, base + (size_t)(j1 + row) * 3 * DD + DD + cc * 8);
                cp16(Vs + nb * 64 * PADW + row * PADW + cc * 8, base + (size_t)(j1 + row) * 3 * DD + 2 * DD + cc * 8);
            }
            cp_commit();
            cp_wait1();
        } else {
            cp_wait0();
        }
        __syncthreads();
        const __nv_bfloat16* K_ = Ks + buf * 64 * PADW;
        const __nv_bfloat16* V_ = Vs + buf * 64 * PADW;

        float s[8][4];
#pragma unroll
        for (int nt = 0; nt < 8; nt++)
#pragma unroll
            for (int q = 0; q < 4; q++) s[nt][q] = 0.f;
#pragma unroll
        for (int kd = 0; kd < 4; kd++) {
            uint32_t a[4];
            ldm_x4(a, smem_u32(Qs + (size_t)(w * 16 + a_r) * PADW + kd * 16 + a_ch));
            uint32_t bb[4][4];
#pragma unroll
            for (int nj = 0; nj < 4; nj++)
                ldm_x4(bb[nj], smem_u32(K_ + (size_t)(nj * 16 + b_r) * PADW + kd * 16 + b_ch));
#pragma unroll
            for (int nt = 0; nt < 8; nt++)
                mma16816(s[nt], a, bb[nt >> 1] + (nt & 1) * 2);
        }

        const float SC = 0.125f * 1.44269504f;
        int j0 = t * 64;
        if (i0 >= XL && j0 + 63 >= i0) {
#pragma unroll
            for (int nt = 0; nt < 8; nt++) {
                int j = j0 + nt * 8 + (lane & 3) * 2;
                s[nt][0] = (j     <= r0g)     ? s[nt][0] * SC : -1e30f;
                s[nt][1] = (j + 1 <= r0g)     ? s[nt][1] * SC : -1e30f;
                s[nt][2] = (j     <= r0g + 8) ? s[nt][2] * SC : -1e30f;
                s[nt][3] = (j + 1 <= r0g + 8) ? s[nt][3] * SC : -1e30f;
            }
        } else {
#pragma unroll
            for (int nt = 0; nt < 8; nt++)
#pragma unroll
                for (int q = 0; q < 4; q++) s[nt][q] *= SC;
        }

        float t0 = -1e30f, t1 = -1e30f;
#pragma unroll
        for (int nt = 0; nt < 8; nt++) {
            t0 = fmaxf(t0, fmaxf(s[nt][0], s[nt][1]));
            t1 = fmaxf(t1, fmaxf(s[nt][2], s[nt][3]));
        }
        t0 = fmaxf(t0, __shfl_xor_sync(0xffffffff, t0, 1));
        t0 = fmaxf(t0, __shfl_xor_sync(0xffffffff, t0, 2));
        t1 = fmaxf(t1, __shfl_xor_sync(0xffffffff, t1, 1));
        t1 = fmaxf(t1, __shfl_xor_sync(0xffffffff, t1, 2));
        float mn0 = fmaxf(m0, t0), mn1 = fmaxf(m1, t1);
        float al0 = exp2f(m0 - mn0), al1 = exp2f(m1 - mn1);
        m0 = mn0; m1 = mn1;
        float rs0 = 0.f, rs1 = 0.f;
#pragma unroll
        for (int nt = 0; nt < 8; nt++) {
            s[nt][0] = exp2f(s[nt][0] - m0); rs0 += s[nt][0];
            s[nt][1] = exp2f(s[nt][1] - m0); rs0 += s[nt][1];
            s[nt][2] = exp2f(s[nt][2] - m1); rs1 += s[nt][2];
            s[nt][3] = exp2f(s[nt][3] - m1); rs1 += s[nt][3];
        }
        rs0 += __shfl_xor_sync(0xffffffff, rs0, 1);
        rs0 += __shfl_xor_sync(0xffffffff, rs0, 2);
        rs1 += __shfl_xor_sync(0xffffffff, rs1, 1);
        rs1 += __shfl_xor_sync(0xffffffff, rs1, 2);
        l0 = l0 * al0 + rs0; l1 = l1 * al1 + rs1;
#pragma unroll
        for (int dt = 0; dt < 8; dt++) {
            o[dt][0] *= al0; o[dt][1] *= al0;
            o[dt][2] *= al1; o[dt][3] *= al1;
        }

        uint32_t pa[4][4];
#pragma unroll
        for (int kt = 0; kt < 4; kt++) {
            pa[kt][0] = pk(s[2 * kt][0], s[2 * kt][1]);
            pa[kt][1] = pk(s[2 * kt][2], s[2 * kt][3]);
            pa[kt][2] = pk(s[2 * kt + 1][0], s[2 * kt + 1][1]);
            pa[kt][3] = pk(s[2 * kt + 1][2], s[2 * kt + 1][3]);
        }

#pragma unroll
        for (int kt = 0; kt < 4; kt++) {
#pragma unroll
            for (int dv = 0; dv < 4; dv++) {
                uint32_t vb[4];
                ldm_x4_t(vb, smem_u32(V_ + (size_t)(kt * 16 + (lane & 15)) * PADW + dv * 16 + (lane >> 4) * 8));
                mma16816(o[dv * 2], pa[kt], vb);
                mma16816(o[dv * 2 + 1], pa[kt], vb + 2);
            }
        }
        __syncthreads();
    }

    float inv0 = 1.f / l0, inv1 = 1.f / l1;
#pragma unroll
    for (int dt = 0; dt < 8; dt++) {
        int cols = h * DH + dt * 8 + (lane & 3) * 2;
        __nv_bfloat162 p0 = __floats2bfloat162_rn(o[dt][0] * inv0, o[dt][1] * inv0);
        __nv_bfloat162 p1 = __floats2bfloat162_rn(o[dt][2] * inv1, o[dt][3] * inv1);
        *(__nv_bfloat162*)(g_attnb + (size_t)(b * SS + r0g) * DD + cols) = p0;
        *(__nv_bfloat162*)(g_attnb + (size_t)(b * SS + r0g + 8) * DD + cols) = p1;
    }
}

// ---------------- streaming fp32 -> bf16 cast ----------------
__global__ void wcast(const float* __restrict__ W, __nv_bfloat16* __restrict__ o, int n4) {
    int stride = gridDim.x * blockDim.x;
    for (int i = blockIdx.x * blockDim.x + threadIdx.x; i < n4; i += stride) {
        float4 v = ((const float4*)W)[i];
        __nv_bfloat162 p0 = __floats2bfloat162_rn(v.x, v.y);
        __nv_bfloat162 p1 = __floats2bfloat162_rn(v.z, v.w);
        uint2 u = make_uint2(*(uint32_t*)&p0, *(uint32_t*)&p1);
        ((uint2*)o)[i] = u;
    }
}
// proj [1024,1025] -> bf16 [1024,1152] zero-padded
__global__ void projcast(const float* __restrict__ W, __nv_bfloat16* __restrict__ o) {
    int k = blockIdx.x;
    for (int n = threadIdx.x; n < NPAD; n += blockDim.x)
        o[(size_t)k * NPAD + n] = (n < CVOC) ? __float2bfloat16(W[(size_t)k * CVOC + n]) : __nv_bfloat16(0.f);
}

// ---------------- embedding + sinusoidal PE ----------------
__global__ void embed_kernel(const int* __restrict__ tokens, const int* __restrict__ codes,
                             const float* __restrict__ tok_emb, const float* __restrict__ audio_emb) {
    int row = blockIdx.x;
    int b = row / SS, s = row % SS;
    const float* src; int pos;
    if (s < XL) { src = tok_emb + (size_t)tokens[b*XL + s] * DD; pos = s; }
    else {
        int sy = s - XL;
        int id = (sy == 0) ? BOS_ID : codes[b*CL + sy - 1];
        src = audio_emb + (size_t)id * DD; pos = sy;
    }
    float* dst = g_h + (size_t)row * DD;
    __nv_bfloat16* dstb = g_hb + (size_t)row * DD;
    const float kinv = 9.210340371976184f / (float)DD;
    for (int d = threadIdx.x; d < DD; d += blockDim.x) {
        float freq = expf(-(float)(d & ~1) * kinv);
        float ang = (float)pos * freq;
        float pe = (d & 1) ? cosf(ang) : sinf(ang);
        float v = src[d] + pe;
        dst[d] = v;
        dstb[d] = __float2bfloat16(v);
    }
}

// ---------------- h = LN(h + p0 + p1 + bias); writes fp32 + bf16 ----------------
__global__ void __launch_bounds__(256) add_ln3(const float* __restrict__ p0,
        const float* __restrict__ p1, const float* __restrict__ bias,
        const float* __restrict__ w, const float* __restrict__ bvec) {
    __shared__ float red[8], red2[8];
    int row = blockIdx.x, tid = threadIdx.x, lane = tid & 31, wid = tid >> 5;

    float4 v = ((const float4*)(g_h + (size_t)row * DD))[tid];
    float4 q0 = ((const float4*)(p0 + (size_t)row * DD))[tid];
    float4 q1 = ((const float4*)(p1 + (size_t)row * DD))[tid];
    float4 bq = ((const float4*)bias)[tid];
    v.x += q0.x + q1.x + bq.x; v.y += q0.y + q1.y + bq.y;
    v.z += q0.z + q1.z + bq.z; v.w += q0.w + q1.w + bq.w;

    float s = v.x + v.y + v.z + v.w;
#pragma unroll
    for (int o = 16; o; o >>= 1) s += __shfl_xor_sync(0xffffffff, s, o);
    if (lane == 0) red[wid] = s;
    __syncthreads();
    float tot = 0.f;
#pragma unroll
    for (int i = 0; i < 8; i++) tot += red[i];
    float mu = tot * (1.f / DD);

    float dx = v.x - mu, dy = v.y - mu, dz = v.z - mu, dw = v.w - mu;
    float s2 = dx * dx + dy * dy + dz * dz + dw * dw;
#pragma unroll
    for (int o = 16; o; o >>= 1) s2 += __shfl_xor_sync(0xffffffff, s2, o);
    if (lane == 0) red2[wid] = s2;
    __syncthreads();
    float tot2 = 0.f;
#pragma unroll
    for (int i = 0; i < 8; i++) tot2 += red2[i];
    float rstd = rsqrtf(tot2 * (1.f / DD) + 1e-5f);

    float4 w4 = ((const float4*)w)[tid];
    float4 b4 = ((const float4*)bvec)[tid];
    float4 out;
    out.x = dx * rstd * w4.x + b4.x;
    out.y = dy * rstd * w4.y + b4.y;
    out.z = dz * rstd * w4.z + b4.z;
    out.w = dw * rstd * w4.w + b4.w;
    ((float4*)(g_h + (size_t)row * DD))[tid] = out;
    __nv_bfloat162 h0 = __floats2bfloat162_rn(out.x, out.y);
    __nv_bfloat162 h1 = __floats2bfloat162_rn(out.z, out.w);
    ((uint2*)(g_hb + (size_t)row * DD))[tid] = make_uint2(*(uint32_t*)&h0, *(uint32_t*)&h1);
}

// ---------------- final LN on audio rows only -> bf16 gather ----------------
__global__ void __launch_bounds__(256) lnf_gather(const float* __restrict__ w,
                                                  const float* __restrict__ bvec) {
    __shared__ float red[8], red2[8];
    int m = blockIdx.x, tid = threadIdx.x, lane = tid & 31, wid = tid >> 5;
    int b = m / YL, t = m % YL;

    float4 v = ((const float4*)(g_h + (size_t)(b * SS + XL + t) * DD))[tid];
    float s = v.x + v.y + v.z + v.w;
#pragma unroll
    for (int o = 16; o; o >>= 1) s += __shfl_xor_sync(0xffffffff, s, o);
    if (lane == 0) red[wid] = s;
    __syncthreads();
    float tot = 0.f;
#pragma unroll
    for (int i = 0; i < 8; i++) tot += red[i];
    float mu = tot * (1.f / DD);

    float dx = v.x - mu, dy = v.y - mu, dz = v.z - mu, dw = v.w - mu;
    float s2 = dx * dx + dy * dy + dz * dz + dw * dw;
#pragma unroll
    for (int o = 16; o; o >>= 1) s2 += __shfl_xor_sync(0xffffffff, s2, o);
    if (lane == 0) red2[wid] = s2;
    __syncthreads();
    float tot2 = 0.f;
#pragma unroll
    for (int i = 0; i < 8; i++) tot2 += red2[i];
    float rstd = rsqrtf(tot2 * (1.f / DD) + 1e-5f);

    float4 w4 = ((const float4*)w)[tid];
    float4 b4 = ((const float4*)bvec)[tid];
    __nv_bfloat162 h0 = __floats2bfloat162_rn(dx * rstd * w4.x + b4.x, dy * rstd * w4.y + b4.y);
    __nv_bfloat162 h1 = __floats2bfloat162_rn(dz * rstd * w4.z + b4.z, dw * rstd * w4.w + b4.w);
    ((uint2*)(g_xb + (size_t)m * DD))[tid] = make_uint2(*(uint32_t*)&h0, *(uint32_t*)&h1);
}

// ---------------- per-row NLL (sums two split-K logit partials) ----------------
__device__ __forceinline__ float blk_reduce_max(float v, float* red) {
    int t = threadIdx.x;
    red[t] = v; __syncthreads();
    for (int s = 128; s > 0; s >>= 1) { if (t < s) red[t] = fmaxf(red[t], red[t + s]); __syncthreads(); }
    float r = red[0]; __syncthreads();
    return r;
}
__device__ __forceinline__ float blk_reduce_sum(float v, float* red) {
    int t = threadIdx.x;
    red[t] = v; __syncthreads();
    for (int s = 128; s > 0; s >>= 1) { if (t < s) red[t] += red[t + s]; __syncthreads(); }
    float r = red[0]; __syncthreads();
    return r;
}
__global__ void nll_kernel(const int* __restrict__ codes) {
    __shared__ float red[256];
    __shared__ float rowbuf[CVOC];
    int m = blockIdx.x;
    int b = m / YL, t = m % YL;
    const float* r0 = g_logits + (size_t)m * NPAD;
    const float* r1 = g_logits + (size_t)PROWS * NPAD + (size_t)m * NPAD;
    int tid = threadIdx.x;

    float lmax = -1e30f;
    for (int j = tid; j < CVOC; j += 256) {
        float v = r0[j] + r1[j];
        rowbuf[j] = v;
        lmax = fmaxf(lmax, v);
    }
    lmax = blk_reduce_max(lmax, red);
    float lsum = 0.f;
    for (int j = tid; j < CVOC; j += 256) lsum += expf(rowbuf[j] - lmax);
    lsum = blk_reduce_sum(lsum, red);
    if (tid == 0) {
        int tgt = (t < CL) ? codes[b * CL + t] : EOS_ID;
        g_nll[m] = lmax + logf(lsum) - rowbuf[tgt];
    }
}

__global__ void mean_kernel(float* __restrict__ out) {
    __shared__ float red[256];
    int tid = threadIdx.x;
    float s = 0.f;
    for (int i = tid; i < PROWS; i += 256) s += g_nll[i];
    s = blk_reduce_sum(s, red);
    if (tid == 0) out[0] = s / (float)PROWS;
}

// ---------------- launch ----------------
extern "C" void kernel_launch(void* const* d_in, const int* in_sizes, int n_in,
                              void* d_out, int out_size) {
    const int*   tokens    = (const int*)d_in[0];
    const int*   codes     = (const int*)d_in[1];
    const float* tok_emb   = (const float*)d_in[2];
    const float* audio_emb = (const float*)d_in[3];
    const float* Wqkv      = (const float*)d_in[4];
    const float* b_qkv     = (const float*)d_in[5];
    const float* Wo        = (const float*)d_in[6];
    const float* b_o       = (const float*)d_in[7];
    const float* W1        = (const float*)d_in[8];
    const float* b1        = (const float*)d_in[9];
    const float* W2        = (const float*)d_in[10];
    const float* b2        = (const float*)d_in[11];
    const float* ln1_w     = (const float*)d_in[12];
    const float* ln1_b     = (const float*)d_in[13];
    const float* ln2_w     = (const float*)d_in[14];
    const float* ln2_b     = (const float*)d_in[15];
    const float* lnf_w     = (const float*)d_in[16];
    const float* lnf_b     = (const float*)d_in[17];
    const float* proj_w    = (const float*)d_in[18];

    float *tmpP, *logitsP;
    __nv_bfloat16 *hbP, *qkvbP, *attnbP, *ffbP, *xbP, *WqkvP, *WoP, *W1P, *W2P, *projP;
    cudaGetSymbolAddress((void**)&hbP, g_hb);
    cudaGetSymbolAddress((void**)&qkvbP, g_qkvb);
    cudaGetSymbolAddress((void**)&attnbP, g_attnb);
    cudaGetSymbolAddress((void**)&tmpP, g_tmp);
    cudaGetSymbolAddress((void**)&ffbP, g_ffb);
    cudaGetSymbolAddress((void**)&xbP, g_xb);
    cudaGetSymbolAddress((void**)&logitsP, g_logits);
    cudaGetSymbolAddress((void**)&WqkvP, g_Wqkv);
    cudaGetSymbolAddress((void**)&WoP, g_Wo);
    cudaGetSymbolAddress((void**)&W1P, g_W1);
    cudaGetSymbolAddress((void**)&W2P, g_W2);
    cudaGetSymbolAddress((void**)&projP, g_proj);

    cudaFuncSetAttribute(gemm_mma<1,0,1,1>, cudaFuncAttributeMaxDynamicSharedMemorySize, GEMM_SMEM);
    cudaFuncSetAttribute(gemm_mma<1,1,1,1>, cudaFuncAttributeMaxDynamicSharedMemorySize, GEMM_SMEM);
    cudaFuncSetAttribute(gemm_mma<0,0,0,2>, cudaFuncAttributeMaxDynamicSharedMemorySize, GEMM_SMEM);
    cudaFuncSetAttribute(flash_attn, cudaFuncAttributeMaxDynamicSharedMemorySize, FLASH_SMEM);

    // weight casts (streaming, no transpose)
    wcast<<<4096, 256>>>(Wqkv, WqkvP, NLAYER*DD*3*DD/4);
    wcast<<<2048, 256>>>(Wo, WoP, NLAYER*DD*DD/4);
    wcast<<<4096, 256>>>(W1, W1P, NLAYER*DD*FFD/4);
    wcast<<<4096, 256>>>(W2, W2P, NLAYER*FFD*DD/4);
    projcast<<<DD, 256>>>(proj_w, projP);

    embed_kernel<<<MROWS, 256>>>(tokens, codes, tok_emb, audio_emb);

    for (int l = 0; l < NLAYER; l++) {
        gemm_mma<1,0,1,1><<<dim3(3*DD/128, MROWS/128, 1), 256, GEMM_SMEM>>>(
            qkvbP, hbP, WqkvP + (size_t)l*DD*3*DD, b_qkv + (size_t)l*3*DD, MROWS, DD, 3*DD);
        flash_attn<<<dim3(SS/128, BB*NH), 256, FLASH_SMEM>>>(qkvbP);
        gemm_mma<0,0,0,2><<<dim3(DD/128, MROWS/128, 2), 256, GEMM_SMEM>>>(
            tmpP, attnbP, WoP + (size_t)l*DD*DD, nullptr, MROWS, DD, DD);
        add_ln3<<<MROWS, 256>>>(tmpP, tmpP + (size_t)MROWS*DD, b_o + (size_t)l*DD,
                                ln1_w + l*DD, ln1_b + l*DD);
        gemm_mma<1,1,1,1><<<dim3(FFD/128, MROWS/128, 1), 256, GEMM_SMEM>>>(
            ffbP, hbP, W1P + (size_t)l*DD*FFD, b1 + (size_t)l*FFD, MROWS, DD, FFD);
        gemm_mma<0,0,0,2><<<dim3(DD/128, MROWS/128, 2), 256, GEMM_SMEM>>>(
            tmpP, ffbP, W2P + (size_t)l*FFD*DD, nullptr, MROWS, FFD, DD);
        add_ln3<<<MROWS, 256>>>(tmpP, tmpP + (size_t)MROWS*DD, b2 + (size_t)l*DD,
                                ln2_w + l*DD, ln2_b + l*DD);
    }

    lnf_gather<<<PROWS, 256>>>(lnf_w, lnf_b);
    gemm_mma<0,0,0,2><<<dim3(NPAD/128, PROWS/128, 2), 256, GEMM_SMEM>>>(
        logitsP, xbP, projP, nullptr, PROWS, DD, NPAD);
    nll_kernel<<<PROWS, 256>>>(codes);
    mean_kernel<<<1, 256>>>((float*)d_out);
}

// round 9
// speedup vs baseline: 8.0555x; 1.0112x over previous
#include <cuda_runtime.h>
#include <cuda_bf16.h>
#include <math.h>
#include <stdint.h>

#define BB 2
#define XL 256
#define CL 767
#define YL 768
#define SS 1024
#define DD 1024
#define FFD 4096
#define NLAYER 6
#define NH 16
#define DH 64
#define CVOC 1025
#define NPAD 1152
#define EOS_ID 1024
#define BOS_ID 1025
#define MROWS (BB*SS)
#define PROWS (BB*YL)

// ---------------- scratch (static device globals; no allocs) ----------------
__device__ float g_h[MROWS*DD];
__device__ __nv_bfloat16 g_hb[MROWS*DD];
__device__ __nv_bfloat16 g_qkvb[MROWS*3*DD];
__device__ __nv_bfloat16 g_attnb[MROWS*DD];
__device__ float g_tmp[MROWS*DD];
__device__ __nv_bfloat16 g_ffb[MROWS*FFD];
__device__ __nv_bfloat16 g_xb[PROWS*DD];
__device__ float g_logits[PROWS*NPAD];
__device__ float g_nll[PROWS];
// bf16 K-major weights [K,N] (no transpose)
__device__ __nv_bfloat16 g_Wqkv[NLAYER*DD*3*DD];
__device__ __nv_bfloat16 g_Wo[NLAYER*DD*DD];
__device__ __nv_bfloat16 g_W1[NLAYER*DD*FFD];
__device__ __nv_bfloat16 g_W2[NLAYER*FFD*DD];
__device__ __nv_bfloat16 g_proj[DD*NPAD];

// ---------------- helpers ----------------
__device__ __forceinline__ uint32_t smem_u32(const void* p) {
    uint32_t a;
    asm("{ .reg .u64 t; cvta.to.shared.u64 t, %1; cvt.u32.u64 %0, t; }" : "=r"(a) : "l"(p));
    return a;
}
__device__ __forceinline__ void cp16(void* smem_dst, const void* gsrc) {
    uint32_t s = smem_u32(smem_dst);
    asm volatile("cp.async.cg.shared.global [%0], [%1], 16;" :: "r"(s), "l"(gsrc));
}
__device__ __forceinline__ void cp_commit() { asm volatile("cp.async.commit_group;" ::: "memory"); }
__device__ __forceinline__ void cp_wait0()  { asm volatile("cp.async.wait_group 0;" ::: "memory"); }
__device__ __forceinline__ void cp_wait1()  { asm volatile("cp.async.wait_group 1;" ::: "memory"); }

__device__ __forceinline__ void ldm_x4(uint32_t* r, uint32_t addr) {
    asm volatile("ldmatrix.sync.aligned.m8n8.x4.shared.b16 {%0,%1,%2,%3}, [%4];"
        : "=r"(r[0]), "=r"(r[1]), "=r"(r[2]), "=r"(r[3]) : "r"(addr));
}
__device__ __forceinline__ void ldm_x4_t(uint32_t* r, uint32_t addr) {
    asm volatile("ldmatrix.sync.aligned.m8n8.x4.trans.shared.b16 {%0,%1,%2,%3}, [%4];"
        : "=r"(r[0]), "=r"(r[1]), "=r"(r[2]), "=r"(r[3]) : "r"(addr));
}
__device__ __forceinline__ void mma16816(float* c, const uint32_t* a, const uint32_t* b) {
    asm volatile("mma.sync.aligned.m16n8k16.row.col.f32.bf16.bf16.f32 "
        "{%0,%1,%2,%3}, {%4,%5,%6,%7}, {%8,%9}, {%0,%1,%2,%3};"
        : "+f"(c[0]), "+f"(c[1]), "+f"(c[2]), "+f"(c[3])
        : "r"(a[0]), "r"(a[1]), "r"(a[2]), "r"(a[3]), "r"(b[0]), "r"(b[1]));
}
__device__ __forceinline__ uint32_t pk(float x, float y) {
    __nv_bfloat162 p = __floats2bfloat162_rn(x, y);
    return *(uint32_t*)&p;
}

#define KCH 64
#define PADW 72                    // A-tile row pad (bf16 elems)
#define PADB 136                   // B-tile row pad (272B: conflict-free trans ldm)
#define ATILE_E (128*PADW)
#define BTILE_E (64*PADB)
#define GEMM_SMEM ((2*ATILE_E + 2*BTILE_E)*2 + 512)

// ---------------- HMMA bf16 GEMM: C[M,N] = A[M,K] @ W[K,N] (+bias)(+relu) ----------------
// grid (N/128, M/128), block 256 (8 warps: 2 M x 4 N; warp tile 64x32)
template<int OUT_BF16, int RELU, int HAS_BIAS>
__global__ void __launch_bounds__(256) gemm_mma(void* __restrict__ Cv,
        const __nv_bfloat16* __restrict__ A, const __nv_bfloat16* __restrict__ W,
        const float* __restrict__ bias, int M, int K, int N) {
    extern __shared__ __nv_bfloat16 sm[];
    __nv_bfloat16* As = sm;                       // [2][128][PADW]
    __nv_bfloat16* Bs = sm + 2 * ATILE_E;         // [2][64][PADB]
    float* biasSm = (float*)(sm + 2 * ATILE_E + 2 * BTILE_E);

    int tid = threadIdx.x;
    int wid = tid >> 5, lane = tid & 31;
    int wm = wid >> 2, wn = wid & 3;
    int m0 = blockIdx.y * 128, n0 = blockIdx.x * 128;

    if (HAS_BIAS && tid < 128) biasSm[tid] = bias[n0 + tid];

    const __nv_bfloat16* gA = A + (size_t)m0 * K;
    const __nv_bfloat16* gB = W + n0;

    float acc[4][4][4];
#pragma unroll
    for (int i = 0; i < 4; i++)
#pragma unroll
        for (int j = 0; j < 4; j++)
#pragma unroll
            for (int q = 0; q < 4; q++) acc[i][j][q] = 0.f;

    const int nch = K / KCH;
#pragma unroll
    for (int i = 0; i < 4; i++) {
        int c = tid + 256 * i;
        int ar = c >> 3, ap = c & 7;
        cp16(As + ar * PADW + ap * 8, gA + (size_t)ar * K + ap * 8);
        int br = c >> 4, bp = c & 15;
        cp16(Bs + br * PADB + bp * 8, gB + (size_t)br * N + bp * 8);
    }
    cp_commit();

    int a_r = (lane & 7) + ((lane >> 3) & 1) * 8;
    int a_ch = (lane >> 4) * 8;

    for (int ic = 0; ic < nch; ic++) {
        int buf = ic & 1;
        cp_wait0();
        __syncthreads();
        if (ic + 1 < nch) {
            const __nv_bfloat16* gA1 = gA + (size_t)(ic + 1) * KCH;
            const __nv_bfloat16* gB1 = gB + (size_t)(ic + 1) * KCH * N;
            __nv_bfloat16* dA = As + (buf ^ 1) * ATILE_E;
            __nv_bfloat16* dB = Bs + (buf ^ 1) * BTILE_E;
#pragma unroll
            for (int i = 0; i < 4; i++) {
                int c = tid + 256 * i;
                int ar = c >> 3, ap = c & 7;
                cp16(dA + ar * PADW + ap * 8, gA1 + (size_t)ar * K + ap * 8);
                int br = c >> 4, bp = c & 15;
                cp16(dB + br * PADB + bp * 8, gB1 + (size_t)br * N + bp * 8);
            }
            cp_commit();
        }

        const __nv_bfloat16* As_ = As + buf * ATILE_E;
        const __nv_bfloat16* Bs_ = Bs + buf * BTILE_E;
#pragma unroll
        for (int ks = 0; ks < 4; ks++) {
            uint32_t a[4][4], b[2][4];
#pragma unroll
            for (int mi = 0; mi < 4; mi++)
                ldm_x4(a[mi], smem_u32(As_ + (size_t)(wm * 64 + mi * 16 + a_r) * PADW + ks * 16 + a_ch));
#pragma unroll
            for (int ni2 = 0; ni2 < 2; ni2++)
                ldm_x4_t(b[ni2], smem_u32(Bs_ + (size_t)(ks * 16 + (lane & 15)) * PADB + wn * 32 + ni2 * 16 + (lane >> 4) * 8));
#pragma unroll
            for (int mi = 0; mi < 4; mi++)
#pragma unroll
                for (int ni = 0; ni < 4; ni++)
                    mma16816(acc[mi][ni], a[mi], b[ni >> 1] + (ni & 1) * 2);
        }
        __syncthreads();
    }

    int rg = lane >> 2, cg = (lane & 3) * 2;
#pragma unroll
    for (int mi = 0; mi < 4; mi++) {
#pragma unroll
        for (int ni = 0; ni < 4; ni++) {
            int colL = wn * 32 + ni * 8 + cg;
            int col = n0 + colL;
            float b0 = HAS_BIAS ? biasSm[colL] : 0.f;
            float b1 = HAS_BIAS ? biasSm[colL + 1] : 0.f;
#pragma unroll
            for (int rh = 0; rh < 2; rh++) {
                int row = m0 + wm * 64 + mi * 16 + rg + rh * 8;
                float v0 = acc[mi][ni][rh * 2 + 0] + b0;
                float v1 = acc[mi][ni][rh * 2 + 1] + b1;
                if (RELU) { v0 = fmaxf(v0, 0.f); v1 = fmaxf(v1, 0.f); }
                if (OUT_BF16) {
                    __nv_bfloat162 p = __floats2bfloat162_rn(v0, v1);
                    *(__nv_bfloat162*)((__nv_bfloat16*)Cv + (size_t)row * N + col) = p;
                } else {
                    *(float2*)((float*)Cv + (size_t)row * N + col) = make_float2(v0, v1);
                }
            }
        }
    }
}

// ---------------- fused flash attention ----------------
#define FLASH_SMEM ((128*PADW + 2*64*PADW + 2*64*PADW) * 2)
__global__ void __launch_bounds__(256) flash_attn(const __nv_bfloat16* __restrict__ qkvb) {
    extern __shared__ __nv_bfloat16 fsm[];
    __nv_bfloat16* Qs = fsm;
    __nv_bfloat16* Ks = fsm + 128 * PADW;
    __nv_bfloat16* Vs = fsm + 128 * PADW + 2 * 64 * PADW;

    int bh = blockIdx.y;
    int b = bh / NH, h = bh % NH;
    int i0 = blockIdx.x * 128;
    int ntile = ((i0 < XL) ? XL : (i0 + 128)) / 64;

    int tid = threadIdx.x, w = tid >> 5, lane = tid & 31;
    const __nv_bfloat16* base = qkvb + (size_t)(b * SS) * 3 * DD + h * DH;

#pragma unroll
    for (int i = 0; i < 4; i++) {
        int c = tid + 256 * i;
        int row = c >> 3, cc = c & 7;
        cp16(Qs + row * PADW + cc * 8, base + (size_t)(i0 + row) * 3 * DD + cc * 8);
    }
#pragma unroll
    for (int i = 0; i < 2; i++) {
        int c = tid + 256 * i;
        int row = c >> 3, cc = c & 7;
        cp16(Ks + row * PADW + cc * 8, base + (size_t)row * 3 * DD + DD + cc * 8);
        cp16(Vs + row * PADW + cc * 8, base + (size_t)row * 3 * DD + 2 * DD + cc * 8);
    }
    cp_commit();

    float m0 = -1e30f, m1 = -1e30f, l0 = 0.f, l1 = 0.f;
    float o[8][4];
#pragma unroll
    for (int dt = 0; dt < 8; dt++)
#pragma unroll
        for (int q = 0; q < 4; q++) o[dt][q] = 0.f;

    int a_r = (lane & 7) + ((lane >> 3) & 1) * 8;
    int a_ch = (lane >> 4) * 8;
    int b_r = (lane & 7) + (lane >> 4) * 8;
    int b_ch = ((lane >> 3) & 1) * 8;
    int r0g = i0 + w * 16 + (lane >> 2);

    for (int t = 0; t < ntile; t++) {
        int buf = t & 1;
        if (t + 1 < ntile) {
            int j1 = (t + 1) * 64, nb = (t + 1) & 1;
#pragma unroll
            for (int i = 0; i < 2; i++) {
                int c = tid + 256 * i;
                int row = c >> 3, cc = c & 7;
                cp16(Ks + nb * 64 * PADW + row * PADW + cc * 8, base + (size_t)(j1 + row) * 3 * DD + DD + cc * 8);
                cp16(Vs + nb * 64 * PADW + row * PADW + cc * 8, base + (size_t)(j1 + row) * 3 * DD + 2 * DD + cc * 8);
            }
            cp_commit();
            cp_wait1();
        } else {
            cp_wait0();
        }
        __syncthreads();
        const __nv_bfloat16* K_ = Ks + buf * 64 * PADW;
        const __nv_bfloat16* V_ = Vs + buf * 64 * PADW;

        float s[8][4];
#pragma unroll
        for (int nt = 0; nt < 8; nt++)
#pragma unroll
            for (int q = 0; q < 4; q++) s[nt][q] = 0.f;
#pragma unroll
        for (int kd = 0; kd < 4; kd++) {
            uint32_t a[4];
            ldm_x4(a, smem_u32(Qs + (size_t)(w * 16 + a_r) * PADW + kd * 16 + a_ch));
            uint32_t bb[4][4];
#pragma unroll
            for (int nj = 0; nj < 4; nj++)
                ldm_x4(bb[nj], smem_u32(K_ + (size_t)(nj * 16 + b_r) * PADW + kd * 16 + b_ch));
#pragma unroll
            for (int nt = 0; nt < 8; nt++)
                mma16816(s[nt], a, bb[nt >> 1] + (nt & 1) * 2);
        }

        const float SC = 0.125f * 1.44269504f;
        int j0 = t * 64;
        if (i0 >= XL && j0 + 63 >= i0) {
#pragma unroll
            for (int nt = 0; nt < 8; nt++) {
                int j = j0 + nt * 8 + (lane & 3) * 2;
                s[nt][0] = (j     <= r0g)     ? s[nt][0] * SC : -1e30f;
                s[nt][1] = (j + 1 <= r0g)     ? s[nt][1] * SC : -1e30f;
                s[nt][2] = (j     <= r0g + 8) ? s[nt][2] * SC : -1e30f;
                s[nt][3] = (j + 1 <= r0g + 8) ? s[nt][3] * SC : -1e30f;
            }
        } else {
#pragma unroll
            for (int nt = 0; nt < 8; nt++)
#pragma unroll
                for (int q = 0; q < 4; q++) s[nt][q] *= SC;
        }

        float t0 = -1e30f, t1 = -1e30f;
#pragma unroll
        for (int nt = 0; nt < 8; nt++) {
            t0 = fmaxf(t0, fmaxf(s[nt][0], s[nt][1]));
            t1 = fmaxf(t1, fmaxf(s[nt][2], s[nt][3]));
        }
        t0 = fmaxf(t0, __shfl_xor_sync(0xffffffff, t0, 1));
        t0 = fmaxf(t0, __shfl_xor_sync(0xffffffff, t0, 2));
        t1 = fmaxf(t1, __shfl_xor_sync(0xffffffff, t1, 1));
        t1 = fmaxf(t1, __shfl_xor_sync(0xffffffff, t1, 2));
        float mn0 = fmaxf(m0, t0), mn1 = fmaxf(m1, t1);
        float al0 = exp2f(m0 - mn0), al1 = exp2f(m1 - mn1);
        m0 = mn0; m1 = mn1;
        float rs0 = 0.f, rs1 = 0.f;
#pragma unroll
        for (int nt = 0; nt < 8; nt++) {
            s[nt][0] = exp2f(s[nt][0] - m0); rs0 += s[nt][0];
            s[nt][1] = exp2f(s[nt][1] - m0); rs0 += s[nt][1];
            s[nt][2] = exp2f(s[nt][2] - m1); rs1 += s[nt][2];
            s[nt][3] = exp2f(s[nt][3] - m1); rs1 += s[nt][3];
        }
        rs0 += __shfl_xor_sync(0xffffffff, rs0, 1);
        rs0 += __shfl_xor_sync(0xffffffff, rs0, 2);
        rs1 += __shfl_xor_sync(0xffffffff, rs1, 1);
        rs1 += __shfl_xor_sync(0xffffffff, rs1, 2);
        l0 = l0 * al0 + rs0; l1 = l1 * al1 + rs1;
#pragma unroll
        for (int dt = 0; dt < 8; dt++) {
            o[dt][0] *= al0; o[dt][1] *= al0;
            o[dt][2] *= al1; o[dt][3] *= al1;
        }

        uint32_t pa[4][4];
#pragma unroll
        for (int kt = 0; kt < 4; kt++) {
            pa[kt][0] = pk(s[2 * kt][0], s[2 * kt][1]);
            pa[kt][1] = pk(s[2 * kt][2], s[2 * kt][3]);
            pa[kt][2] = pk(s[2 * kt + 1][0], s[2 * kt + 1][1]);
            pa[kt][3] = pk(s[2 * kt + 1][2], s[2 * kt + 1][3]);
        }

#pragma unroll
        for (int kt = 0; kt < 4; kt++) {
#pragma unroll
            for (int dv = 0; dv < 4; dv++) {
                uint32_t vb[4];
                ldm_x4_t(vb, smem_u32(V_ + (size_t)(kt * 16 + (lane & 15)) * PADW + dv * 16 + (lane >> 4) * 8));
                mma16816(o[dv * 2], pa[kt], vb);
                mma16816(o[dv * 2 + 1], pa[kt], vb + 2);
            }
        }
        __syncthreads();
    }

    float inv0 = 1.f / l0, inv1 = 1.f / l1;
#pragma unroll
    for (int dt = 0; dt < 8; dt++) {
        int cols = h * DH + dt * 8 + (lane & 3) * 2;
        __nv_bfloat162 p0 = __floats2bfloat162_rn(o[dt][0] * inv0, o[dt][1] * inv0);
        __nv_bfloat162 p1 = __floats2bfloat162_rn(o[dt][2] * inv1, o[dt][3] * inv1);
        *(__nv_bfloat162*)(g_attnb + (size_t)(b * SS + r0g) * DD + cols) = p0;
        *(__nv_bfloat162*)(g_attnb + (size_t)(b * SS + r0g + 8) * DD + cols) = p1;
    }
}

// ---------------- streaming fp32 -> bf16 cast ----------------
__global__ void wcast(const float* __restrict__ W, __nv_bfloat16* __restrict__ o, int n4) {
    int stride = gridDim.x * blockDim.x;
    for (int i = blockIdx.x * blockDim.x + threadIdx.x; i < n4; i += stride) {
        float4 v = ((const float4*)W)[i];
        __nv_bfloat162 p0 = __floats2bfloat162_rn(v.x, v.y);
        __nv_bfloat162 p1 = __floats2bfloat162_rn(v.z, v.w);
        ((uint2*)o)[i] = make_uint2(*(uint32_t*)&p0, *(uint32_t*)&p1);
    }
}
__global__ void projcast(const float* __restrict__ W, __nv_bfloat16* __restrict__ o) {
    int k = blockIdx.x;
    for (int n = threadIdx.x; n < NPAD; n += blockDim.x)
        o[(size_t)k * NPAD + n] = (n < CVOC) ? __float2bfloat16(W[(size_t)k * CVOC + n]) : __nv_bfloat16(0.f);
}

// ---------------- embedding + sinusoidal PE ----------------
__global__ void embed_kernel(const int* __restrict__ tokens, const int* __restrict__ codes,
                             const float* __restrict__ tok_emb, const float* __restrict__ audio_emb) {
    int row = blockIdx.x;
    int b = row / SS, s = row % SS;
    const float* src; int pos;
    if (s < XL) { src = tok_emb + (size_t)tokens[b*XL + s] * DD; pos = s; }
    else {
        int sy = s - XL;
        int id = (sy == 0) ? BOS_ID : codes[b*CL + sy - 1];
        src = audio_emb + (size_t)id * DD; pos = sy;
    }
    float* dst = g_h + (size_t)row * DD;
    __nv_bfloat16* dstb = g_hb + (size_t)row * DD;
    const float kinv = 9.210340371976184f / (float)DD;
    for (int d = threadIdx.x; d < DD; d += blockDim.x) {
        float freq = expf(-(float)(d & ~1) * kinv);
        float ang = (float)pos * freq;
        float pe = (d & 1) ? cosf(ang) : sinf(ang);
        float v = src[d] + pe;
        dst[d] = v;
        dstb[d] = __float2bfloat16(v);
    }
}

// ---------------- h = LN(h + p0); writes fp32 + bf16 ----------------
__global__ void __launch_bounds__(256) add_ln2(const float* __restrict__ p0,
        const float* __restrict__ w, const float* __restrict__ bvec) {
    __shared__ float red[8], red2[8];
    int row = blockIdx.x, tid = threadIdx.x, lane = tid & 31, wid = tid >> 5;

    float4 v = ((const float4*)(g_h + (size_t)row * DD))[tid];
    float4 q0 = ((const float4*)(p0 + (size_t)row * DD))[tid];
    v.x += q0.x; v.y += q0.y; v.z += q0.z; v.w += q0.w;

    float s = v.x + v.y + v.z + v.w;
#pragma unroll
    for (int o = 16; o; o >>= 1) s += __shfl_xor_sync(0xffffffff, s, o);
    if (lane == 0) red[wid] = s;
    __syncthreads();
    float tot = 0.f;
#pragma unroll
    for (int i = 0; i < 8; i++) tot += red[i];
    float mu = tot * (1.f / DD);

    float dx = v.x - mu, dy = v.y - mu, dz = v.z - mu, dw = v.w - mu;
    float s2 = dx * dx + dy * dy + dz * dz + dw * dw;
#pragma unroll
    for (int o = 16; o; o >>= 1) s2 += __shfl_xor_sync(0xffffffff, s2, o);
    if (lane == 0) red2[wid] = s2;
    __syncthreads();
    float tot2 = 0.f;
#pragma unroll
    for (int i = 0; i < 8; i++) tot2 += red2[i];
    float rstd = rsqrtf(tot2 * (1.f / DD) + 1e-5f);

    float4 w4 = ((const float4*)w)[tid];
    float4 b4 = ((const float4*)bvec)[tid];
    float4 out;
    out.x = dx * rstd * w4.x + b4.x;
    out.y = dy * rstd * w4.y + b4.y;
    out.z = dz * rstd * w4.z + b4.z;
    out.w = dw * rstd * w4.w + b4.w;
    ((float4*)(g_h + (size_t)row * DD))[tid] = out;
    __nv_bfloat162 h0 = __floats2bfloat162_rn(out.x, out.y);
    __nv_bfloat162 h1 = __floats2bfloat162_rn(out.z, out.w);
    ((uint2*)(g_hb + (size_t)row * DD))[tid] = make_uint2(*(uint32_t*)&h0, *(uint32_t*)&h1);
}

// ---------------- final LN on audio rows only -> bf16 gather ----------------
__global__ void __launch_bounds__(256) lnf_gather(const float* __restrict__ w,
                                                  const float* __restrict__ bvec) {
    __shared__ float red[8], red2[8];
    int m = blockIdx.x, tid = threadIdx.x, lane = tid & 31, wid = tid >> 5;
    int b = m / YL, t = m % YL;

    float4 v = ((const float4*)(g_h + (size_t)(b * SS + XL + t) * DD))[tid];
    float s = v.x + v.y + v.z + v.w;
#pragma unroll
    for (int o = 16; o; o >>= 1) s += __shfl_xor_sync(0xffffffff, s, o);
    if (lane == 0) red[wid] = s;
    __syncthreads();
    float tot = 0.f;
#pragma unroll
    for (int i = 0; i < 8; i++) tot += red[i];
    float mu = tot * (1.f / DD);

    float dx = v.x - mu, dy = v.y - mu, dz = v.z - mu, dw = v.w - mu;
    float s2 = dx * dx + dy * dy + dz * dz + dw * dw;
#pragma unroll
    for (int o = 16; o; o >>= 1) s2 += __shfl_xor_sync(0xffffffff, s2, o);
    if (lane == 0) red2[wid] = s2;
    __syncthreads();
    float tot2 = 0.f;
#pragma unroll
    for (int i = 0; i < 8; i++) tot2 += red2[i];
    float rstd = rsqrtf(tot2 * (1.f / DD) + 1e-5f);

    float4 w4 = ((const float4*)w)[tid];
    float4 b4 = ((const float4*)bvec)[tid];
    __nv_bfloat162 h0 = __floats2bfloat162_rn(dx * rstd * w4.x + b4.x, dy * rstd * w4.y + b4.y);
    __nv_bfloat162 h1 = __floats2bfloat162_rn(dz * rstd * w4.z + b4.z, dw * rstd * w4.w + b4.w);
    ((uint2*)(g_xb + (size_t)m * DD))[tid] = make_uint2(*(uint32_t*)&h0, *(uint32_t*)&h1);
}

// ---------------- per-row NLL ----------------
__device__ __forceinline__ float blk_reduce_max(float v, float* red) {
    int t = threadIdx.x;
    red[t] = v; __syncthreads();
    for (int s = 128; s > 0; s >>= 1) { if (t < s) red[t] = fmaxf(red[t], red[t + s]); __syncthreads(); }
    float r = red[0]; __syncthreads();
    return r;
}
__device__ __forceinline__ float blk_reduce_sum(float v, float* red) {
    int t = threadIdx.x;
    red[t] = v; __syncthreads();
    for (int s = 128; s > 0; s >>= 1) { if (t < s) red[t] += red[t + s]; __syncthreads(); }
    float r = red[0]; __syncthreads();
    return r;
}
__global__ void nll_kernel(const int* __restrict__ codes) {
    __shared__ float red[256];
    int m = blockIdx.x;
    int b = m / YL, t = m % YL;
    const float* row = g_logits + (size_t)m * NPAD;
    int tid = threadIdx.x;

    float lmax = -1e30f;
    for (int j = tid; j < CVOC; j += 256) lmax = fmaxf(lmax, row[j]);
    lmax = blk_reduce_max(lmax, red);
    float lsum = 0.f;
    for (int j = tid; j < CVOC; j += 256) lsum += expf(row[j] - lmax);
    lsum = blk_reduce_sum(lsum, red);
    if (tid == 0) {
        int tgt = (t < CL) ? codes[b * CL + t] : EOS_ID;
        g_nll[m] = lmax + logf(lsum) - row[tgt];
    }
}

__global__ void mean_kernel(float* __restrict__ out) {
    __shared__ float red[256];
    int tid = threadIdx.x;
    float s = 0.f;
    for (int i = tid; i < PROWS; i += 256) s += g_nll[i];
    s = blk_reduce_sum(s, red);
    if (tid == 0) out[0] = s / (float)PROWS;
}

// ---------------- launch ----------------
extern "C" void kernel_launch(void* const* d_in, const int* in_sizes, int n_in,
                              void* d_out, int out_size) {
    const int*   tokens    = (const int*)d_in[0];
    const int*   codes     = (const int*)d_in[1];
    const float* tok_emb   = (const float*)d_in[2];
    const float* audio_emb = (const float*)d_in[3];
    const float* Wqkv      = (const float*)d_in[4];
    const float* b_qkv     = (const float*)d_in[5];
    const float* Wo        = (const float*)d_in[6];
    const float* b_o       = (const float*)d_in[7];
    const float* W1        = (const float*)d_in[8];
    const float* b1        = (const float*)d_in[9];
    const float* W2        = (const float*)d_in[10];
    const float* b2        = (const float*)d_in[11];
    const float* ln1_w     = (const float*)d_in[12];
    const float* ln1_b     = (const float*)d_in[13];
    const float* ln2_w     = (const float*)d_in[14];
    const float* ln2_b     = (const float*)d_in[15];
    const float* lnf_w     = (const float*)d_in[16];
    const float* lnf_b     = (const float*)d_in[17];
    const float* proj_w    = (const float*)d_in[18];

    float *tmpP, *logitsP;
    __nv_bfloat16 *hbP, *qkvbP, *attnbP, *ffbP, *xbP, *WqkvP, *WoP, *W1P, *W2P, *projP;
    cudaGetSymbolAddress((void**)&hbP, g_hb);
    cudaGetSymbolAddress((void**)&qkvbP, g_qkvb);
    cudaGetSymbolAddress((void**)&attnbP, g_attnb);
    cudaGetSymbolAddress((void**)&tmpP, g_tmp);
    cudaGetSymbolAddress((void**)&ffbP, g_ffb);
    cudaGetSymbolAddress((void**)&xbP, g_xb);
    cudaGetSymbolAddress((void**)&logitsP, g_logits);
    cudaGetSymbolAddress((void**)&WqkvP, g_Wqkv);
    cudaGetSymbolAddress((void**)&WoP, g_Wo);
    cudaGetSymbolAddress((void**)&W1P, g_W1);
    cudaGetSymbolAddress((void**)&W2P, g_W2);
    cudaGetSymbolAddress((void**)&projP, g_proj);

    cudaFuncSetAttribute(gemm_mma<1,0,1>, cudaFuncAttributeMaxDynamicSharedMemorySize, GEMM_SMEM);
    cudaFuncSetAttribute(gemm_mma<1,1,1>, cudaFuncAttributeMaxDynamicSharedMemorySize, GEMM_SMEM);
    cudaFuncSetAttribute(gemm_mma<0,0,1>, cudaFuncAttributeMaxDynamicSharedMemorySize, GEMM_SMEM);
    cudaFuncSetAttribute(gemm_mma<0,0,0>, cudaFuncAttributeMaxDynamicSharedMemorySize, GEMM_SMEM);
    cudaFuncSetAttribute(flash_attn, cudaFuncAttributeMaxDynamicSharedMemorySize, FLASH_SMEM);

    wcast<<<4096, 256>>>(Wqkv, WqkvP, NLAYER*DD*3*DD/4);
    wcast<<<2048, 256>>>(Wo, WoP, NLAYER*DD*DD/4);
    wcast<<<4096, 256>>>(W1, W1P, NLAYER*DD*FFD/4);
    wcast<<<4096, 256>>>(W2, W2P, NLAYER*FFD*DD/4);
    projcast<<<DD, 256>>>(proj_w, projP);

    embed_kernel<<<MROWS, 256>>>(tokens, codes, tok_emb, audio_emb);

    for (int l = 0; l < NLAYER; l++) {
        gemm_mma<1,0,1><<<dim3(3*DD/128, MROWS/128), 256, GEMM_SMEM>>>(
            qkvbP, hbP, WqkvP + (size_t)l*DD*3*DD, b_qkv + (size_t)l*3*DD, MROWS, DD, 3*DD);
        flash_attn<<<dim3(SS/128, BB*NH), 256, FLASH_SMEM>>>(qkvbP);
        gemm_mma<0,0,1><<<dim3(DD/128, MROWS/128), 256, GEMM_SMEM>>>(
            tmpP, attnbP, WoP + (size_t)l*DD*DD, b_o + (size_t)l*DD, MROWS, DD, DD);
        add_ln2<<<MROWS, 256>>>(tmpP, ln1_w + l*DD, ln1_b + l*DD);
        gemm_mma<1,1,1><<<dim3(FFD/128, MROWS/128), 256, GEMM_SMEM>>>(
            ffbP, hbP, W1P + (size_t)l*DD*FFD, b1 + (size_t)l*FFD, MROWS, DD, FFD);
        gemm_mma<0,0,1><<<dim3(DD/128, MROWS/128), 256, GEMM_SMEM>>>(
            tmpP, ffbP, W2P + (size_t)l*FFD*DD, b2 + (size_t)l*DD, MROWS, FFD, DD);
        add_ln2<<<MROWS, 256>>>(tmpP, ln2_w + l*DD, ln2_b + l*DD);
    }

    lnf_gather<<<PROWS, 256>>>(lnf_w, lnf_b);
    gemm_mma<0,0,0><<<dim3(NPAD/128, PROWS/128), 256, GEMM_SMEM>>>(
        logitsP, xbP, projP, nullptr, PROWS, DD, NPAD);
    nll_kernel<<<PROWS, 256>>>(codes);
    mean_kernel<<<1, 256>>>((float*)d_out);
}

// round 10
// speedup vs baseline: 8.0640x; 1.0011x over previous
#include <cuda_runtime.h>
#include <cuda_bf16.h>
#include <math.h>
#include <stdint.h>

#define BB 2
#define XL 256
#define CL 767
#define YL 768
#define SS 1024
#define DD 1024
#define FFD 4096
#define NLAYER 6
#define NH 16
#define DH 64
#define CVOC 1025
#define NPAD 1152
#define EOS_ID 1024
#define BOS_ID 1025
#define MROWS (BB*SS)
#define PROWS (BB*YL)

// ---------------- scratch (static device globals; no allocs) ----------------
__device__ float g_h[MROWS*DD];
__device__ __nv_bfloat16 g_hb[MROWS*DD];
__device__ __nv_bfloat16 g_qkvb[MROWS*3*DD];
__device__ __nv_bfloat16 g_attnb[MROWS*DD];
__device__ float g_tmp[MROWS*DD];
__device__ __nv_bfloat16 g_ffb[MROWS*FFD];
__device__ __nv_bfloat16 g_xb[PROWS*DD];
__device__ float g_logits[PROWS*NPAD];
__device__ float g_nll[PROWS];
// bf16 K-major weights [K,N] (no transpose)
__device__ __nv_bfloat16 g_Wqkv[NLAYER*DD*3*DD];
__device__ __nv_bfloat16 g_Wo[NLAYER*DD*DD];
__device__ __nv_bfloat16 g_W1[NLAYER*DD*FFD];
__device__ __nv_bfloat16 g_W2[NLAYER*FFD*DD];
__device__ __nv_bfloat16 g_proj[DD*NPAD];

// ---------------- helpers ----------------
__device__ __forceinline__ uint32_t smem_u32(const void* p) {
    uint32_t a;
    asm("{ .reg .u64 t; cvta.to.shared.u64 t, %1; cvt.u32.u64 %0, t; }" : "=r"(a) : "l"(p));
    return a;
}
__device__ __forceinline__ void cp16(void* smem_dst, const void* gsrc) {
    uint32_t s = smem_u32(smem_dst);
    asm volatile("cp.async.cg.shared.global [%0], [%1], 16;" :: "r"(s), "l"(gsrc));
}
__device__ __forceinline__ void cp_commit() { asm volatile("cp.async.commit_group;" ::: "memory"); }
__device__ __forceinline__ void cp_wait0()  { asm volatile("cp.async.wait_group 0;" ::: "memory"); }
__device__ __forceinline__ void cp_wait1()  { asm volatile("cp.async.wait_group 1;" ::: "memory"); }

__device__ __forceinline__ void ldm_x4(uint32_t* r, uint32_t addr) {
    asm volatile("ldmatrix.sync.aligned.m8n8.x4.shared.b16 {%0,%1,%2,%3}, [%4];"
        : "=r"(r[0]), "=r"(r[1]), "=r"(r[2]), "=r"(r[3]) : "r"(addr));
}
__device__ __forceinline__ void ldm_x4_t(uint32_t* r, uint32_t addr) {
    asm volatile("ldmatrix.sync.aligned.m8n8.x4.trans.shared.b16 {%0,%1,%2,%3}, [%4];"
        : "=r"(r[0]), "=r"(r[1]), "=r"(r[2]), "=r"(r[3]) : "r"(addr));
}
__device__ __forceinline__ void mma16816(float* c, const uint32_t* a, const uint32_t* b) {
    asm volatile("mma.sync.aligned.m16n8k16.row.col.f32.bf16.bf16.f32 "
        "{%0,%1,%2,%3}, {%4,%5,%6,%7}, {%8,%9}, {%0,%1,%2,%3};"
        : "+f"(c[0]), "+f"(c[1]), "+f"(c[2]), "+f"(c[3])
        : "r"(a[0]), "r"(a[1]), "r"(a[2]), "r"(a[3]), "r"(b[0]), "r"(b[1]));
}
__device__ __forceinline__ uint32_t pk(float x, float y) {
    __nv_bfloat162 p = __floats2bfloat162_rn(x, y);
    return *(uint32_t*)&p;
}

#define KCH 64
#define PADW 72                    // A-tile row pad (bf16 elems)
#define PADB 136                   // B-tile row pad (272B: conflict-free trans ldm)
#define ATILE_E (128*PADW)
#define BTILE_E (64*PADB)
#define GEMM_SMEM ((2*ATILE_E + 2*BTILE_E)*2 + 512)

// ---------------- HMMA bf16 GEMM: C[M,N] = A[M,K] @ W[K,N] (+bias)(+relu) ----------------
// grid (N/128, M/128), block 256 (8 warps: 2 M x 4 N; warp tile 64x32), 2 CTAs/SM
template<int OUT_BF16, int RELU, int HAS_BIAS>
__global__ void __launch_bounds__(256, 2) gemm_mma(void* __restrict__ Cv,
        const __nv_bfloat16* __restrict__ A, const __nv_bfloat16* __restrict__ W,
        const float* __restrict__ bias, int M, int K, int N) {
    extern __shared__ __nv_bfloat16 sm[];
    __nv_bfloat16* As = sm;                       // [2][128][PADW]
    __nv_bfloat16* Bs = sm + 2 * ATILE_E;         // [2][64][PADB]
    float* biasSm = (float*)(sm + 2 * ATILE_E + 2 * BTILE_E);

    int tid = threadIdx.x;
    int wid = tid >> 5, lane = tid & 31;
    int wm = wid >> 2, wn = wid & 3;
    int m0 = blockIdx.y * 128, n0 = blockIdx.x * 128;

    if (HAS_BIAS && tid < 128) biasSm[tid] = bias[n0 + tid];

    const __nv_bfloat16* gA = A + (size_t)m0 * K;
    const __nv_bfloat16* gB = W + n0;

    float acc[4][4][4];
#pragma unroll
    for (int i = 0; i < 4; i++)
#pragma unroll
        for (int j = 0; j < 4; j++)
#pragma unroll
            for (int q = 0; q < 4; q++) acc[i][j][q] = 0.f;

    const int nch = K / KCH;
#pragma unroll
    for (int i = 0; i < 4; i++) {
        int c = tid + 256 * i;
        int ar = c >> 3, ap = c & 7;
        cp16(As + ar * PADW + ap * 8, gA + (size_t)ar * K + ap * 8);
        int br = c >> 4, bp = c & 15;
        cp16(Bs + br * PADB + bp * 8, gB + (size_t)br * N + bp * 8);
    }
    cp_commit();

    int a_r = (lane & 7) + ((lane >> 3) & 1) * 8;
    int a_ch = (lane >> 4) * 8;

    for (int ic = 0; ic < nch; ic++) {
        int buf = ic & 1;
        cp_wait0();
        __syncthreads();
        if (ic + 1 < nch) {
            const __nv_bfloat16* gA1 = gA + (size_t)(ic + 1) * KCH;
            const __nv_bfloat16* gB1 = gB + (size_t)(ic + 1) * KCH * N;
            __nv_bfloat16* dA = As + (buf ^ 1) * ATILE_E;
            __nv_bfloat16* dB = Bs + (buf ^ 1) * BTILE_E;
#pragma unroll
            for (int i = 0; i < 4; i++) {
                int c = tid + 256 * i;
                int ar = c >> 3, ap = c & 7;
                cp16(dA + ar * PADW + ap * 8, gA1 + (size_t)ar * K + ap * 8);
                int br = c >> 4, bp = c & 15;
                cp16(dB + br * PADB + bp * 8, gB1 + (size_t)br * N + bp * 8);
            }
            cp_commit();
        }

        const __nv_bfloat16* As_ = As + buf * ATILE_E;
        const __nv_bfloat16* Bs_ = Bs + buf * BTILE_E;
#pragma unroll
        for (int ks = 0; ks < 4; ks++) {
            uint32_t a[4][4], b[2][4];
#pragma unroll
            for (int mi = 0; mi < 4; mi++)
                ldm_x4(a[mi], smem_u32(As_ + (size_t)(wm * 64 + mi * 16 + a_r) * PADW + ks * 16 + a_ch));
#pragma unroll
            for (int ni2 = 0; ni2 < 2; ni2++)
                ldm_x4_t(b[ni2], smem_u32(Bs_ + (size_t)(ks * 16 + (lane & 15)) * PADB + wn * 32 + ni2 * 16 + (lane >> 4) * 8));
#pragma unroll
            for (int mi = 0; mi < 4; mi++)
#pragma unroll
                for (int ni = 0; ni < 4; ni++)
                    mma16816(acc[mi][ni], a[mi], b[ni >> 1] + (ni & 1) * 2);
        }
        __syncthreads();
    }

    int rg = lane >> 2, cg = (lane & 3) * 2;
#pragma unroll
    for (int mi = 0; mi < 4; mi++) {
#pragma unroll
        for (int ni = 0; ni < 4; ni++) {
            int colL = wn * 32 + ni * 8 + cg;
            int col = n0 + colL;
            float b0 = HAS_BIAS ? biasSm[colL] : 0.f;
            float b1 = HAS_BIAS ? biasSm[colL + 1] : 0.f;
#pragma unroll
            for (int rh = 0; rh < 2; rh++) {
                int row = m0 + wm * 64 + mi * 16 + rg + rh * 8;
                float v0 = acc[mi][ni][rh * 2 + 0] + b0;
                float v1 = acc[mi][ni][rh * 2 + 1] + b1;
                if (RELU) { v0 = fmaxf(v0, 0.f); v1 = fmaxf(v1, 0.f); }
                if (OUT_BF16) {
                    __nv_bfloat162 p = __floats2bfloat162_rn(v0, v1);
                    *(__nv_bfloat162*)((__nv_bfloat16*)Cv + (size_t)row * N + col) = p;
                } else {
                    *(float2*)((float*)Cv + (size_t)row * N + col) = make_float2(v0, v1);
                }
            }
        }
    }
}

// ---------------- fused flash attention ----------------
#define FLASH_SMEM ((128*PADW + 2*64*PADW + 2*64*PADW) * 2)
__global__ void __launch_bounds__(256, 2) flash_attn(const __nv_bfloat16* __restrict__ qkvb) {
    extern __shared__ __nv_bfloat16 fsm[];
    __nv_bfloat16* Qs = fsm;
    __nv_bfloat16* Ks = fsm + 128 * PADW;
    __nv_bfloat16* Vs = fsm + 128 * PADW + 2 * 64 * PADW;

    int bh = blockIdx.y;
    int b = bh / NH, h = bh % NH;
    int i0 = blockIdx.x * 128;
    int ntile = ((i0 < XL) ? XL : (i0 + 128)) / 64;

    int tid = threadIdx.x, w = tid >> 5, lane = tid & 31;
    const __nv_bfloat16* base = qkvb + (size_t)(b * SS) * 3 * DD + h * DH;

#pragma unroll
    for (int i = 0; i < 4; i++) {
        int c = tid + 256 * i;
        int row = c >> 3, cc = c & 7;
        cp16(Qs + row * PADW + cc * 8, base + (size_t)(i0 + row) * 3 * DD + cc * 8);
    }
#pragma unroll
    for (int i = 0; i < 2; i++) {
        int c = tid + 256 * i;
        int row = c >> 3, cc = c & 7;
        cp16(Ks + row * PADW + cc * 8, base + (size_t)row * 3 * DD + DD + cc * 8);
        cp16(Vs + row * PADW + cc * 8, base + (size_t)row * 3 * DD + 2 * DD + cc * 8);
    }
    cp_commit();

    float m0 = -1e30f, m1 = -1e30f, l0 = 0.f, l1 = 0.f;
    float o[8][4];
#pragma unroll
    for (int dt = 0; dt < 8; dt++)
#pragma unroll
        for (int q = 0; q < 4; q++) o[dt][q] = 0.f;

    int a_r = (lane & 7) + ((lane >> 3) & 1) * 8;
    int a_ch = (lane >> 4) * 8;
    int b_r = (lane & 7) + (lane >> 4) * 8;
    int b_ch = ((lane >> 3) & 1) * 8;
    int r0g = i0 + w * 16 + (lane >> 2);

    for (int t = 0; t < ntile; t++) {
        int buf = t & 1;
        if (t + 1 < ntile) {
            int j1 = (t + 1) * 64, nb = (t + 1) & 1;
#pragma unroll
            for (int i = 0; i < 2; i++) {
                int c = tid + 256 * i;
                int row = c >> 3, cc = c & 7;
                cp16(Ks + nb * 64 * PADW + row * PADW + cc * 8, base + (size_t)(j1 + row) * 3 * DD + DD + cc * 8);
                cp16(Vs + nb * 64 * PADW + row * PADW + cc * 8, base + (size_t)(j1 + row) * 3 * DD + 2 * DD + cc * 8);
            }
            cp_commit();
            cp_wait1();
        } else {
            cp_wait0();
        }
        __syncthreads();
        const __nv_bfloat16* K_ = Ks + buf * 64 * PADW;
        const __nv_bfloat16* V_ = Vs + buf * 64 * PADW;

        float s[8][4];
#pragma unroll
        for (int nt = 0; nt < 8; nt++)
#pragma unroll
            for (int q = 0; q < 4; q++) s[nt][q] = 0.f;
#pragma unroll
        for (int kd = 0; kd < 4; kd++) {
            uint32_t a[4];
            ldm_x4(a, smem_u32(Qs + (size_t)(w * 16 + a_r) * PADW + kd * 16 + a_ch));
            uint32_t bb[4][4];
#pragma unroll
            for (int nj = 0; nj < 4; nj++)
                ldm_x4(bb[nj], smem_u32(K_ + (size_t)(nj * 16 + b_r) * PADW + kd * 16 + b_ch));
#pragma unroll
            for (int nt = 0; nt < 8; nt++)
                mma16816(s[nt], a, bb[nt >> 1] + (nt & 1) * 2);
        }

        const float SC = 0.125f * 1.44269504f;
        int j0 = t * 64;
        if (i0 >= XL && j0 + 63 >= i0) {
#pragma unroll
            for (int nt = 0; nt < 8; nt++) {
                int j = j0 + nt * 8 + (lane & 3) * 2;
                s[nt][0] = (j     <= r0g)     ? s[nt][0] * SC : -1e30f;
                s[nt][1] = (j + 1 <= r0g)     ? s[nt][1] * SC : -1e30f;
                s[nt][2] = (j     <= r0g + 8) ? s[nt][2] * SC : -1e30f;
                s[nt][3] = (j + 1 <= r0g + 8) ? s[nt][3] * SC : -1e30f;
            }
        } else {
#pragma unroll
            for (int nt = 0; nt < 8; nt++)
#pragma unroll
                for (int q = 0; q < 4; q++) s[nt][q] *= SC;
        }

        float t0 = -1e30f, t1 = -1e30f;
#pragma unroll
        for (int nt = 0; nt < 8; nt++) {
            t0 = fmaxf(t0, fmaxf(s[nt][0], s[nt][1]));
            t1 = fmaxf(t1, fmaxf(s[nt][2], s[nt][3]));
        }
        t0 = fmaxf(t0, __shfl_xor_sync(0xffffffff, t0, 1));
        t0 = fmaxf(t0, __shfl_xor_sync(0xffffffff, t0, 2));
        t1 = fmaxf(t1, __shfl_xor_sync(0xffffffff, t1, 1));
        t1 = fmaxf(t1, __shfl_xor_sync(0xffffffff, t1, 2));
        float mn0 = fmaxf(m0, t0), mn1 = fmaxf(m1, t1);
        float al0 = exp2f(m0 - mn0), al1 = exp2f(m1 - mn1);
        m0 = mn0; m1 = mn1;
        float rs0 = 0.f, rs1 = 0.f;
#pragma unroll
        for (int nt = 0; nt < 8; nt++) {
            s[nt][0] = exp2f(s[nt][0] - m0); rs0 += s[nt][0];
            s[nt][1] = exp2f(s[nt][1] - m0); rs0 += s[nt][1];
            s[nt][2] = exp2f(s[nt][2] - m1); rs1 += s[nt][2];
            s[nt][3] = exp2f(s[nt][3] - m1); rs1 += s[nt][3];
        }
        rs0 += __shfl_xor_sync(0xffffffff, rs0, 1);
        rs0 += __shfl_xor_sync(0xffffffff, rs0, 2);
        rs1 += __shfl_xor_sync(0xffffffff, rs1, 1);
        rs1 += __shfl_xor_sync(0xffffffff, rs1, 2);
        l0 = l0 * al0 + rs0; l1 = l1 * al1 + rs1;
#pragma unroll
        for (int dt = 0; dt < 8; dt++) {
            o[dt][0] *= al0; o[dt][1] *= al0;
            o[dt][2] *= al1; o[dt][3] *= al1;
        }

        uint32_t pa[4][4];
#pragma unroll
        for (int kt = 0; kt < 4; kt++) {
            pa[kt][0] = pk(s[2 * kt][0], s[2 * kt][1]);
            pa[kt][1] = pk(s[2 * kt][2], s[2 * kt][3]);
            pa[kt][2] = pk(s[2 * kt + 1][0], s[2 * kt + 1][1]);
            pa[kt][3] = pk(s[2 * kt + 1][2], s[2 * kt + 1][3]);
        }

#pragma unroll
        for (int kt = 0; kt < 4; kt++) {
#pragma unroll
            for (int dv = 0; dv < 4; dv++) {
                uint32_t vb[4];
                ldm_x4_t(vb, smem_u32(V_ + (size_t)(kt * 16 + (lane & 15)) * PADW + dv * 16 + (lane >> 4) * 8));
                mma16816(o[dv * 2], pa[kt], vb);
                mma16816(o[dv * 2 + 1], pa[kt], vb + 2);
            }
        }
        __syncthreads();
    }

    float inv0 = 1.f / l0, inv1 = 1.f / l1;
#pragma unroll
    for (int dt = 0; dt < 8; dt++) {
        int cols = h * DH + dt * 8 + (lane & 3) * 2;
        __nv_bfloat162 p0 = __floats2bfloat162_rn(o[dt][0] * inv0, o[dt][1] * inv0);
        __nv_bfloat162 p1 = __floats2bfloat162_rn(o[dt][2] * inv1, o[dt][3] * inv1);
        *(__nv_bfloat162*)(g_attnb + (size_t)(b * SS + r0g) * DD + cols) = p0;
        *(__nv_bfloat162*)(g_attnb + (size_t)(b * SS + r0g + 8) * DD + cols) = p1;
    }
}

// ---------------- streaming fp32 -> bf16 cast (all weights in one launch) ----------------
#define N4_QKV (NLAYER*DD*3*DD/4)
#define N4_WO  (NLAYER*DD*DD/4)
#define N4_W1  (NLAYER*DD*FFD/4)
#define N4_W2  (NLAYER*FFD*DD/4)
__global__ void wcast_all(const float* __restrict__ Wqkv, const float* __restrict__ Wo,
                          const float* __restrict__ W1, const float* __restrict__ W2) {
    const int total = N4_QKV + N4_WO + N4_W1 + N4_W2;
    int stride = gridDim.x * blockDim.x;
    for (int i = blockIdx.x * blockDim.x + threadIdx.x; i < total; i += stride) {
        const float4* src;
        uint2* dst;
        int j = i;
        if (j < N4_QKV) { src = (const float4*)Wqkv; dst = (uint2*)g_Wqkv; }
        else if ((j -= N4_QKV) < N4_WO) { src = (const float4*)Wo; dst = (uint2*)g_Wo; }
        else if ((j -= N4_WO) < N4_W1) { src = (const float4*)W1; dst = (uint2*)g_W1; }
        else { j -= N4_W1; src = (const float4*)W2; dst = (uint2*)g_W2; }
        float4 v = src[j];
        __nv_bfloat162 p0 = __floats2bfloat162_rn(v.x, v.y);
        __nv_bfloat162 p1 = __floats2bfloat162_rn(v.z, v.w);
        dst[j] = make_uint2(*(uint32_t*)&p0, *(uint32_t*)&p1);
    }
}
__global__ void projcast(const float* __restrict__ W, __nv_bfloat16* __restrict__ o) {
    int k = blockIdx.x;
    for (int n = threadIdx.x; n < NPAD; n += blockDim.x)
        o[(size_t)k * NPAD + n] = (n < CVOC) ? __float2bfloat16(W[(size_t)k * CVOC + n]) : __nv_bfloat16(0.f);
}

// ---------------- embedding + sinusoidal PE ----------------
__global__ void embed_kernel(const int* __restrict__ tokens, const int* __restrict__ codes,
                             const float* __restrict__ tok_emb, const float* __restrict__ audio_emb) {
    int row = blockIdx.x;
    int b = row / SS, s = row % SS;
    const float* src; int pos;
    if (s < XL) { src = tok_emb + (size_t)tokens[b*XL + s] * DD; pos = s; }
    else {
        int sy = s - XL;
        int id = (sy == 0) ? BOS_ID : codes[b*CL + sy - 1];
        src = audio_emb + (size_t)id * DD; pos = sy;
    }
    float* dst = g_h + (size_t)row * DD;
    __nv_bfloat16* dstb = g_hb + (size_t)row * DD;
    const float kinv = 9.210340371976184f / (float)DD;
    for (int d = threadIdx.x; d < DD; d += blockDim.x) {
        float freq = expf(-(float)(d & ~1) * kinv);
        float ang = (float)pos * freq;
        float pe = (d & 1) ? cosf(ang) : sinf(ang);
        float v = src[d] + pe;
        dst[d] = v;
        dstb[d] = __float2bfloat16(v);
    }
}

// ---------------- h = LN(h + p0); writes fp32 + bf16 ----------------
__global__ void __launch_bounds__(256) add_ln2(const float* __restrict__ p0,
        const float* __restrict__ w, const float* __restrict__ bvec) {
    __shared__ float red[8], red2[8];
    int row = blockIdx.x, tid = threadIdx.x, lane = tid & 31, wid = tid >> 5;

    float4 v = ((const float4*)(g_h + (size_t)row * DD))[tid];
    float4 q0 = ((const float4*)(p0 + (size_t)row * DD))[tid];
    v.x += q0.x; v.y += q0.y; v.z += q0.z; v.w += q0.w;

    float s = v.x + v.y + v.z + v.w;
#pragma unroll
    for (int o = 16; o; o >>= 1) s += __shfl_xor_sync(0xffffffff, s, o);
    if (lane == 0) red[wid] = s;
    __syncthreads();
    float tot = 0.f;
#pragma unroll
    for (int i = 0; i < 8; i++) tot += red[i];
    float mu = tot * (1.f / DD);

    float dx = v.x - mu, dy = v.y - mu, dz = v.z - mu, dw = v.w - mu;
    float s2 = dx * dx + dy * dy + dz * dz + dw * dw;
#pragma unroll
    for (int o = 16; o; o >>= 1) s2 += __shfl_xor_sync(0xffffffff, s2, o);
    if (lane == 0) red2[wid] = s2;
    __syncthreads();
    float tot2 = 0.f;
#pragma unroll
    for (int i = 0; i < 8; i++) tot2 += red2[i];
    float rstd = rsqrtf(tot2 * (1.f / DD) + 1e-5f);

    float4 w4 = ((const float4*)w)[tid];
    float4 b4 = ((const float4*)bvec)[tid];
    float4 out;
    out.x = dx * rstd * w4.x + b4.x;
    out.y = dy * rstd * w4.y + b4.y;
    out.z = dz * rstd * w4.z + b4.z;
    out.w = dw * rstd * w4.w + b4.w;
    ((float4*)(g_h + (size_t)row * DD))[tid] = out;
    __nv_bfloat162 h0 = __floats2bfloat162_rn(out.x, out.y);
    __nv_bfloat162 h1 = __floats2bfloat162_rn(out.z, out.w);
    ((uint2*)(g_hb + (size_t)row * DD))[tid] = make_uint2(*(uint32_t*)&h0, *(uint32_t*)&h1);
}

// ---------------- final LN on audio rows only -> bf16 gather ----------------
__global__ void __launch_bounds__(256) lnf_gather(const float* __restrict__ w,
                                                  const float* __restrict__ bvec) {
    __shared__ float red[8], red2[8];
    int m = blockIdx.x, tid = threadIdx.x, lane = tid & 31, wid = tid >> 5;
    int b = m / YL, t = m % YL;

    float4 v = ((const float4*)(g_h + (size_t)(b * SS + XL + t) * DD))[tid];
    float s = v.x + v.y + v.z + v.w;
#pragma unroll
    for (int o = 16; o; o >>= 1) s += __shfl_xor_sync(0xffffffff, s, o);
    if (lane == 0) red[wid] = s;
    __syncthreads();
    float tot = 0.f;
#pragma unroll
    for (int i = 0; i < 8; i++) tot += red[i];
    float mu = tot * (1.f / DD);

    float dx = v.x - mu, dy = v.y - mu, dz = v.z - mu, dw = v.w - mu;
    float s2 = dx * dx + dy * dy + dz * dz + dw * dw;
#pragma unroll
    for (int o = 16; o; o >>= 1) s2 += __shfl_xor_sync(0xffffffff, s2, o);
    if (lane == 0) red2[wid] = s2;
    __syncthreads();
    float tot2 = 0.f;
#pragma unroll
    for (int i = 0; i < 8; i++) tot2 += red2[i];
    float rstd = rsqrtf(tot2 * (1.f / DD) + 1e-5f);

    float4 w4 = ((const float4*)w)[tid];
    float4 b4 = ((const float4*)bvec)[tid];
    __nv_bfloat162 h0 = __floats2bfloat162_rn(dx * rstd * w4.x + b4.x, dy * rstd * w4.y + b4.y);
    __nv_bfloat162 h1 = __floats2bfloat162_rn(dz * rstd * w4.z + b4.z, dw * rstd * w4.w + b4.w);
    ((uint2*)(g_xb + (size_t)m * DD))[tid] = make_uint2(*(uint32_t*)&h0, *(uint32_t*)&h1);
}

// ---------------- per-row NLL ----------------
__device__ __forceinline__ float blk_reduce_max(float v, float* red) {
    int t = threadIdx.x;
    red[t] = v; __syncthreads();
    for (int s = 128; s > 0; s >>= 1) { if (t < s) red[t] = fmaxf(red[t], red[t + s]); __syncthreads(); }
    float r = red[0]; __syncthreads();
    return r;
}
__device__ __forceinline__ float blk_reduce_sum(float v, float* red) {
    int t = threadIdx.x;
    red[t] = v; __syncthreads();
    for (int s = 128; s > 0; s >>= 1) { if (t < s) red[t] += red[t + s]; __syncthreads(); }
    float r = red[0]; __syncthreads();
    return r;
}
__global__ void nll_kernel(const int* __restrict__ codes) {
    __shared__ float red[256];
    int m = blockIdx.x;
    int b = m / YL, t = m % YL;
    const float* row = g_logits + (size_t)m * NPAD;
    int tid = threadIdx.x;

    float lmax = -1e30f;
    for (int j = tid; j < CVOC; j += 256) lmax = fmaxf(lmax, row[j]);
    lmax = blk_reduce_max(lmax, red);
    float lsum = 0.f;
    for (int j = tid; j < CVOC; j += 256) lsum += expf(row[j] - lmax);
    lsum = blk_reduce_sum(lsum, red);
    if (tid == 0) {
        int tgt = (t < CL) ? codes[b * CL + t] : EOS_ID;
        g_nll[m] = lmax + logf(lsum) - row[tgt];
    }
}

__global__ void mean_kernel(float* __restrict__ out) {
    __shared__ float red[256];
    int tid = threadIdx.x;
    float s = 0.f;
    for (int i = tid; i < PROWS; i += 256) s += g_nll[i];
    s = blk_reduce_sum(s, red);
    if (tid == 0) out[0] = s / (float)PROWS;
}

// ---------------- launch ----------------
extern "C" void kernel_launch(void* const* d_in, const int* in_sizes, int n_in,
                              void* d_out, int out_size) {
    const int*   tokens    = (const int*)d_in[0];
    const int*   codes     = (const int*)d_in[1];
    const float* tok_emb   = (const float*)d_in[2];
    const float* audio_emb = (const float*)d_in[3];
    const float* Wqkv      = (const float*)d_in[4];
    const float* b_qkv     = (const float*)d_in[5];
    const float* Wo        = (const float*)d_in[6];
    const float* b_o       = (const float*)d_in[7];
    const float* W1        = (const float*)d_in[8];
    const float* b1        = (const float*)d_in[9];
    const float* W2        = (const float*)d_in[10];
    const float* b2        = (const float*)d_in[11];
    const float* ln1_w     = (const float*)d_in[12];
    const float* ln1_b     = (const float*)d_in[13];
    const float* ln2_w     = (const float*)d_in[14];
    const float* ln2_b     = (const float*)d_in[15];
    const float* lnf_w     = (const float*)d_in[16];
    const float* lnf_b     = (const float*)d_in[17];
    const float* proj_w    = (const float*)d_in[18];

    float *tmpP, *logitsP;
    __nv_bfloat16 *hbP, *qkvbP, *attnbP, *ffbP, *xbP, *WqkvP, *WoP, *W1P, *W2P, *projP;
    cudaGetSymbolAddress((void**)&hbP, g_hb);
    cudaGetSymbolAddress((void**)&qkvbP, g_qkvb);
    cudaGetSymbolAddress((void**)&attnbP, g_attnb);
    cudaGetSymbolAddress((void**)&tmpP, g_tmp);
    cudaGetSymbolAddress((void**)&ffbP, g_ffb);
    cudaGetSymbolAddress((void**)&xbP, g_xb);
    cudaGetSymbolAddress((void**)&logitsP, g_logits);
    cudaGetSymbolAddress((void**)&WqkvP, g_Wqkv);
    cudaGetSymbolAddress((void**)&WoP, g_Wo);
    cudaGetSymbolAddress((void**)&W1P, g_W1);
    cudaGetSymbolAddress((void**)&W2P, g_W2);
    cudaGetSymbolAddress((void**)&projP, g_proj);

    cudaFuncSetAttribute(gemm_mma<1,0,1>, cudaFuncAttributeMaxDynamicSharedMemorySize, GEMM_SMEM);
    cudaFuncSetAttribute(gemm_mma<1,1,1>, cudaFuncAttributeMaxDynamicSharedMemorySize, GEMM_SMEM);
    cudaFuncSetAttribute(gemm_mma<0,0,1>, cudaFuncAttributeMaxDynamicSharedMemorySize, GEMM_SMEM);
    cudaFuncSetAttribute(gemm_mma<0,0,0>, cudaFuncAttributeMaxDynamicSharedMemorySize, GEMM_SMEM);
    cudaFuncSetAttribute(flash_attn, cudaFuncAttributeMaxDynamicSharedMemorySize, FLASH_SMEM);

    wcast_all<<<2048, 256>>>(Wqkv, Wo, W1, W2);
    projcast<<<DD, 256>>>(proj_w, projP);

    embed_kernel<<<MROWS, 256>>>(tokens, codes, tok_emb, audio_emb);

    for (int l = 0; l < NLAYER; l++) {
        gemm_mma<1,0,1><<<dim3(3*DD/128, MROWS/128), 256, GEMM_SMEM>>>(
            qkvbP, hbP, WqkvP + (size_t)l*DD*3*DD, b_qkv + (size_t)l*3*DD, MROWS, DD, 3*DD);
        flash_attn<<<dim3(SS/128, BB*NH), 256, FLASH_SMEM>>>(qkvbP);
        gemm_mma<0,0,1><<<dim3(DD/128, MROWS/128), 256, GEMM_SMEM>>>(
            tmpP, attnbP, WoP + (size_t)l*DD*DD, b_o + (size_t)l*DD, MROWS, DD, DD);
        add_ln2<<<MROWS, 256>>>(tmpP, ln1_w + l*DD, ln1_b + l*DD);
        gemm_mma<1,1,1><<<dim3(FFD/128, MROWS/128), 256, GEMM_SMEM>>>(
            ffbP, hbP, W1P + (size_t)l*DD*FFD, b1 + (size_t)l*FFD, MROWS, DD, FFD);
        gemm_mma<0,0,1><<<dim3(DD/128, MROWS/128), 256, GEMM_SMEM>>>(
            tmpP, ffbP, W2P + (size_t)l*FFD*DD, b2 + (size_t)l*DD, MROWS, FFD, DD);
        add_ln2<<<MROWS, 256>>>(tmpP, ln2_w + l*DD, ln2_b + l*DD);
    }

    lnf_gather<<<PROWS, 256>>>(lnf_w, lnf_b);
    gemm_mma<0,0,0><<<dim3(NPAD/128, PROWS/128), 256, GEMM_SMEM>>>(
        logitsP, xbP, projP, nullptr, PROWS, DD, NPAD);
    nll_kernel<<<PROWS, 256>>>(codes);
    mean_kernel<<<1, 256>>>((float*)d_out);
}